// round 1
// baseline (speedup 1.0000x reference)
#include <cuda_runtime.h>
#include <stdint.h>

#define N 4096
#define D1 512
#define D2H 1024
#define KNN 10

#define BM 128
#define BN 128
#define BK 16
#define TM 8
#define TN 8
#define NTHREADS 256
#define NTILES (N / BM)                    // 32
#define NBLK ((NTILES * (NTILES + 1)) / 2) // 528
#define MASKW (N / 64)                     // 64 words per row

// ---- scratch (device globals; no allocation allowed) ----
__device__ float g_d2[(size_t)N * N];                 // 64 MB pairwise squared distances
__device__ unsigned long long g_mask[(size_t)N * MASKW]; // symmetric anchor bitmask (2 MB)
__device__ int g_asum;                                // sum(anchor)
__device__ float g_sq[N];                             // row sum of squares (original)
__device__ float g_rn[N];                             // 1/max(||hidden_i||, eps)

// ---------------------------------------------------------------------------
__global__ void k_zero() {
    int i = blockIdx.x * blockDim.x + threadIdx.x;
    const int total = N * MASKW;
    for (; i < total; i += gridDim.x * blockDim.x) g_mask[i] = 0ull;
    if (blockIdx.x == 0 && threadIdx.x == 0) g_asum = 0;
}

// one warp per row: sq for original, rn for hidden
__global__ void k_rowstats(const float* __restrict__ orig, const float* __restrict__ hid) {
    int w = (blockIdx.x * blockDim.x + threadIdx.x) >> 5;
    int lane = threadIdx.x & 31;
    if (w < N) {
        const float4* p = (const float4*)(orig + (size_t)w * D1);
        float s = 0.f;
        #pragma unroll 4
        for (int c = lane; c < D1 / 4; c += 32) {
            float4 v = p[c];
            s += v.x * v.x + v.y * v.y + v.z * v.z + v.w * v.w;
        }
        #pragma unroll
        for (int o = 16; o; o >>= 1) s += __shfl_down_sync(0xFFFFFFFFu, s, o);
        if (lane == 0) g_sq[w] = s;
    } else if (w < 2 * N) {
        int r = w - N;
        const float4* p = (const float4*)(hid + (size_t)r * D2H);
        float s = 0.f;
        #pragma unroll 8
        for (int c = lane; c < D2H / 4; c += 32) {
            float4 v = p[c];
            s += v.x * v.x + v.y * v.y + v.z * v.z + v.w * v.w;
        }
        #pragma unroll
        for (int o = 16; o; o >>= 1) s += __shfl_down_sync(0xFFFFFFFFu, s, o);
        if (lane == 0) g_rn[r] = 1.0f / fmaxf(sqrtf(s), 1e-12f);
    }
}

// map linear block id -> (bi, bj) with bi <= bj (upper triangle of tile grid)
__device__ __forceinline__ void tri_map(int t, int& bi, int& bj) {
    int i = 0, rem = t, span = NTILES;
    while (rem >= span) { rem -= span; i++; span--; }
    bi = i;
    bj = i + rem;
}

// A (row-major [N,KD]) times its own transpose: C[i0+.,j0+.] = A_i . A_j
template <int KD>
__device__ __forceinline__ void gemm_nt(const float* __restrict__ A, int i0, int j0,
                                        int ty, int tx,
                                        float (*As)[BM], float (*Bs)[BN],
                                        float acc[TM][TN]) {
    int tid = ty * 16 + tx;
    int lr = tid >> 1;        // row within tile 0..127
    int lc = (tid & 1) * 8;   // k offset 0 or 8

    for (int kk = 0; kk < KD; kk += BK) {
        const float4* ap = (const float4*)(A + (size_t)(i0 + lr) * KD + kk + lc);
        float4 a0 = ap[0], a1 = ap[1];
        const float4* bp = (const float4*)(A + (size_t)(j0 + lr) * KD + kk + lc);
        float4 b0 = bp[0], b1 = bp[1];
        __syncthreads();
        As[lc + 0][lr] = a0.x; As[lc + 1][lr] = a0.y; As[lc + 2][lr] = a0.z; As[lc + 3][lr] = a0.w;
        As[lc + 4][lr] = a1.x; As[lc + 5][lr] = a1.y; As[lc + 6][lr] = a1.z; As[lc + 7][lr] = a1.w;
        Bs[lc + 0][lr] = b0.x; Bs[lc + 1][lr] = b0.y; Bs[lc + 2][lr] = b0.z; Bs[lc + 3][lr] = b0.w;
        Bs[lc + 4][lr] = b1.x; Bs[lc + 5][lr] = b1.y; Bs[lc + 6][lr] = b1.z; Bs[lc + 7][lr] = b1.w;
        __syncthreads();
        #pragma unroll
        for (int k = 0; k < BK; k++) {
            float ar[TM], br[TN];
            const float4* av = (const float4*)&As[k][ty * TM];
            const float4* bv = (const float4*)&Bs[k][tx * TN];
            float4 av0 = av[0], av1 = av[1];
            float4 bv0 = bv[0], bv1 = bv[1];
            ar[0] = av0.x; ar[1] = av0.y; ar[2] = av0.z; ar[3] = av0.w;
            ar[4] = av1.x; ar[5] = av1.y; ar[6] = av1.z; ar[7] = av1.w;
            br[0] = bv0.x; br[1] = bv0.y; br[2] = bv0.z; br[3] = bv0.w;
            br[4] = bv1.x; br[5] = bv1.y; br[6] = bv1.z; br[7] = bv1.w;
            #pragma unroll
            for (int u = 0; u < TM; u++)
                #pragma unroll
                for (int v = 0; v < TN; v++)
                    acc[u][v] += ar[u] * br[v];
        }
    }
    __syncthreads();
}

// GEMM 1: squared distances d2 = sq_i + sq_j - 2 * (orig_i . orig_j), clamped at 0
__global__ __launch_bounds__(NTHREADS) void k_gemm_d2(const float* __restrict__ orig) {
    __shared__ float As[BK][BM];
    __shared__ float Bs[BK][BN];
    int bi, bj;
    tri_map(blockIdx.x, bi, bj);
    int i0 = bi * BM, j0 = bj * BN;
    int tx = threadIdx.x & 15, ty = threadIdx.x >> 4;
    float acc[TM][TN] = {};
    gemm_nt<D1>(orig, i0, j0, ty, tx, As, Bs, acc);

    float sqi[TM], sqj[TN];
    #pragma unroll
    for (int u = 0; u < TM; u++) sqi[u] = g_sq[i0 + ty * TM + u];
    #pragma unroll
    for (int v = 0; v < TN; v++) sqj[v] = g_sq[j0 + tx * TN + v];

    #pragma unroll
    for (int u = 0; u < TM; u++) {
        int i = i0 + ty * TM + u;
        #pragma unroll
        for (int v = 0; v < TN; v++) {
            int j = j0 + tx * TN + v;
            float d2 = fmaxf(sqi[u] + sqj[v] - 2.0f * acc[u][v], 0.0f);
            g_d2[(size_t)i * N + j] = d2;
            if (bi != bj) g_d2[(size_t)j * N + i] = d2;
        }
    }
}

// per-row top-K (smallest (value,index) lexicographic) -> symmetric bitmask
__global__ __launch_bounds__(NTHREADS) void k_knn() {
    int row = blockIdx.x;
    int tid = threadIdx.x;
    unsigned long long top[KNN];
    #pragma unroll
    for (int t = 0; t < KNN; t++) top[t] = ~0ull;

    const float* dr = g_d2 + (size_t)row * N;
    for (int c = tid; c < N; c += NTHREADS) {
        unsigned long long key =
            ((unsigned long long)__float_as_uint(dr[c]) << 32) | (unsigned)c;
        if (key < top[KNN - 1]) {
            int p = KNN - 1;
            while (p > 0 && top[p - 1] > key) { top[p] = top[p - 1]; p--; }
            top[p] = key;
        }
    }

    __shared__ unsigned long long lists[NTHREADS][KNN];
    #pragma unroll
    for (int t = 0; t < KNN; t++) lists[tid][t] = top[t];
    __syncthreads();

    for (int s = NTHREADS / 2; s > 0; s >>= 1) {
        if (tid < s) {
            unsigned long long a[KNN], b[KNN], m[KNN];
            #pragma unroll
            for (int t = 0; t < KNN; t++) { a[t] = lists[tid][t]; b[t] = lists[tid + s][t]; }
            int ia = 0, ib = 0;
            #pragma unroll
            for (int t = 0; t < KNN; t++)
                m[t] = (a[ia] <= b[ib]) ? a[ia++] : b[ib++]; // ia,ib <= 9 while picking
            #pragma unroll
            for (int t = 0; t < KNN; t++) lists[tid][t] = m[t];
        }
        __syncthreads();
    }

    if (tid < KNN) {
        unsigned long long key = lists[0][tid];
        unsigned j = (unsigned)key;
        atomicOr(&g_mask[(size_t)row * MASKW + (j >> 6)], 1ull << (j & 63));
        atomicOr(&g_mask[(size_t)j * MASKW + (row >> 6)], 1ull << (row & 63));
    }
}

__global__ void k_count() {
    int i = blockIdx.x * blockDim.x + threadIdx.x;
    int cnt = 0;
    const int total = N * MASKW;
    for (; i < total; i += gridDim.x * blockDim.x) cnt += __popcll(g_mask[i]);
    #pragma unroll
    for (int o = 16; o; o >>= 1) cnt += __shfl_down_sync(0xFFFFFFFFu, cnt, o);
    if ((threadIdx.x & 31) == 0 && cnt) atomicAdd(&g_asum, cnt);
}

// GEMM 2: cosine sim + masked/scaled outputs (non_anchor first, anchor second)
__global__ __launch_bounds__(NTHREADS) void k_gemm_out(const float* __restrict__ hid,
                                                       float* __restrict__ out) {
    __shared__ float As[BK][BM];
    __shared__ float Bs[BK][BN];
    __shared__ unsigned long long mrow[BM][2]; // anchor bits for rows i0.., cols j0..j0+127
    int bi, bj;
    tri_map(blockIdx.x, bi, bj);
    int i0 = bi * BM, j0 = bj * BN;
    int tx = threadIdx.x & 15, ty = threadIdx.x >> 4;
    float acc[TM][TN] = {};
    gemm_nt<D2H>(hid, i0, j0, ty, tx, As, Bs, acc);

    {
        int tid = threadIdx.x;
        mrow[tid >> 1][tid & 1] =
            g_mask[(size_t)(i0 + (tid >> 1)) * MASKW + (j0 >> 6) + (tid & 1)];
    }
    __syncthreads();

    float asum = (float)g_asum;
    float Nw = 0.5f / asum;                                    // (1-ALPHA)/a_sum
    float Nb = 1.0f / ((float)N * (float)N - 2.0f * asum);     // 1/(sum(non_anchor)-a_sum)

    float rni[TM], rnj[TN];
    #pragma unroll
    for (int u = 0; u < TM; u++) rni[u] = g_rn[i0 + ty * TM + u];
    #pragma unroll
    for (int v = 0; v < TN; v++) rnj[v] = g_rn[j0 + tx * TN + v];

    const size_t NN = (size_t)N * N;
    #pragma unroll
    for (int u = 0; u < TM; u++) {
        int i = i0 + ty * TM + u;
        #pragma unroll
        for (int v = 0; v < TN; v++) {
            int j = j0 + tx * TN + v;
            float C = acc[u][v] * rni[u] * rnj[v];
            unsigned a = (unsigned)((mrow[ty * TM + u][(j & 127) >> 6] >> (j & 63)) & 1ull);
            float na = a ? 0.0f : Nb * C;
            float an = a ? Nw * C : 0.0f;
            out[(size_t)i * N + j] = na;
            out[NN + (size_t)i * N + j] = an;
            if (bi != bj) {
                out[(size_t)j * N + i] = na;
                out[NN + (size_t)j * N + i] = an;
            }
        }
    }
}

// ---------------------------------------------------------------------------
extern "C" void kernel_launch(void* const* d_in, const int* in_sizes, int n_in,
                              void* d_out, int out_size) {
    const float* orig = (const float*)d_in[0]; // [4096, 512]
    const float* hid  = (const float*)d_in[1]; // [4096, 1024]
    float* out = (float*)d_out;                // [2, 4096, 4096]

    k_zero<<<256, 256>>>();
    k_rowstats<<<1024, 256>>>(orig, hid);      // 8192 warps: 4096 sq + 4096 rn
    k_gemm_d2<<<NBLK, NTHREADS>>>(orig);
    k_knn<<<N, NTHREADS>>>();
    k_count<<<256, 256>>>();
    k_gemm_out<<<NBLK, NTHREADS>>>(hid, out);
}

// round 3
// speedup vs baseline: 2.8475x; 2.8475x over previous
#include <cuda_runtime.h>
#include <cuda_bf16.h>
#include <stdint.h>

#define N 4096
#define D1 512
#define D2H 1024
#define KNN 10
#define MASKW (N / 64)
#define BM 128
#define NTILES (N / BM)                    // 32
#define NBLK ((NTILES * (NTILES + 1)) / 2) // 528
#define CSTR 129                           // smem C tile stride (floats)
#define DYN_SMEM (128 * CSTR * 4)          // 66048 B >= 2*32768 stage bufs

// ---------------- scratch (device globals; no allocation allowed) ----------
__device__ __align__(16) float g_d2[(size_t)N * N];      // 64 MB
__device__ unsigned long long g_mask[(size_t)N * MASKW]; // 2 MB
__device__ int g_asum;
__device__ float g_sq[N];
__device__ float g_rn[N];
__device__ __align__(16) __nv_bfloat16 g_ahi[(size_t)N * D1];
__device__ __align__(16) __nv_bfloat16 g_alo[(size_t)N * D1];
__device__ __align__(16) __nv_bfloat16 g_bhi[(size_t)N * D2H];
__device__ __align__(16) __nv_bfloat16 g_blo[(size_t)N * D2H];

// ---------------- helpers ----------------------------------------------------
__device__ __forceinline__ uint32_t smem_u32(const void* p) {
    uint32_t a;
    asm("{ .reg .u64 t; cvta.to.shared.u64 t, %1; cvt.u32.u64 %0, t; }" : "=r"(a) : "l"(p));
    return a;
}
#define SWZ(x) ((uint32_t)(x) ^ ((((uint32_t)(x)) >> 3) & 0x70))

__device__ __forceinline__ void cp16(uint32_t s, const void* g) {
    asm volatile("cp.async.cg.shared.global [%0], [%1], 16;" :: "r"(s), "l"(g));
}
#define CP_COMMIT() asm volatile("cp.async.commit_group;" ::: "memory")
#define CP_WAIT0() asm volatile("cp.async.wait_group 0;" ::: "memory")
#define CP_WAIT1() asm volatile("cp.async.wait_group 1;" ::: "memory")

__device__ __forceinline__ void ldsm4(uint32_t& r0, uint32_t& r1, uint32_t& r2, uint32_t& r3,
                                      uint32_t addr) {
    asm volatile("ldmatrix.sync.aligned.m8n8.x4.shared.b16 {%0,%1,%2,%3}, [%4];"
                 : "=r"(r0), "=r"(r1), "=r"(r2), "=r"(r3) : "r"(addr));
}
__device__ __forceinline__ void mma16816(float c[4], const uint32_t a[4],
                                         uint32_t b0, uint32_t b1) {
    asm volatile("mma.sync.aligned.m16n8k16.row.col.f32.bf16.bf16.f32 "
                 "{%0,%1,%2,%3}, {%4,%5,%6,%7}, {%8,%9}, {%0,%1,%2,%3};"
                 : "+f"(c[0]), "+f"(c[1]), "+f"(c[2]), "+f"(c[3])
                 : "r"(a[0]), "r"(a[1]), "r"(a[2]), "r"(a[3]), "r"(b0), "r"(b1));
}

__device__ __forceinline__ void tri_map(int t, int& bi, int& bj) {
    int i = 0, rem = t, span = NTILES;
    while (rem >= span) { rem -= span; i++; span--; }
    bi = i;
    bj = i + rem;
}

// ---------------- small kernels ----------------------------------------------
__global__ void k_zero() {
    int i = blockIdx.x * blockDim.x + threadIdx.x;
    const int total = N * MASKW;
    for (; i < total; i += gridDim.x * blockDim.x) g_mask[i] = 0ull;
    if (blockIdx.x == 0 && threadIdx.x == 0) g_asum = 0;
}

__global__ void k_split(const float* __restrict__ orig, const float* __restrict__ hid) {
    int idx = blockIdx.x * blockDim.x + threadIdx.x;
    int stride = gridDim.x * blockDim.x;
    const int TA = N * D1, TB = N * D2H;
    for (int i = idx; i < TA; i += stride) {
        float x = orig[i];
        __nv_bfloat16 h = __float2bfloat16(x);
        g_ahi[i] = h;
        g_alo[i] = __float2bfloat16(x - __bfloat162float(h));
    }
    for (int i = idx; i < TB; i += stride) {
        float x = hid[i];
        __nv_bfloat16 h = __float2bfloat16(x);
        g_bhi[i] = h;
        g_blo[i] = __float2bfloat16(x - __bfloat162float(h));
    }
}

__global__ void k_rowstats(const float* __restrict__ orig, const float* __restrict__ hid) {
    int w = (blockIdx.x * blockDim.x + threadIdx.x) >> 5;
    int lane = threadIdx.x & 31;
    if (w < N) {
        const float4* p = (const float4*)(orig + (size_t)w * D1);
        float s = 0.f;
        #pragma unroll 4
        for (int c = lane; c < D1 / 4; c += 32) {
            float4 v = p[c];
            s += v.x * v.x + v.y * v.y + v.z * v.z + v.w * v.w;
        }
        #pragma unroll
        for (int o = 16; o; o >>= 1) s += __shfl_down_sync(0xFFFFFFFFu, s, o);
        if (lane == 0) g_sq[w] = s;
    } else if (w < 2 * N) {
        int r = w - N;
        const float4* p = (const float4*)(hid + (size_t)r * D2H);
        float s = 0.f;
        #pragma unroll 8
        for (int c = lane; c < D2H / 4; c += 32) {
            float4 v = p[c];
            s += v.x * v.x + v.y * v.y + v.z * v.z + v.w * v.w;
        }
        #pragma unroll
        for (int o = 16; o; o >>= 1) s += __shfl_down_sync(0xFFFFFFFFu, s, o);
        if (lane == 0) g_rn[r] = 1.0f / fmaxf(sqrtf(s), 1e-12f);
    }
}

// ---------------- HMMA mainloop ------------------------------------------------
// acc[2][8][4] per warp (32x64 warp tile); CTA tile 128x128, warps 4(M) x 2(N).
// K' = NSEG*KSRC; segment s: NSEG==4: A=(s>>1?lo:hi), B=(s&1?lo:hi)  [exact]
//                 NSEG==3: A=(s==2?lo:hi), B=(s==1?lo:hi)            [drop lo*lo]
template <int KSRC, int NSEG>
__device__ __forceinline__ void mma_mainloop(const __nv_bfloat16* __restrict__ hi,
                                             const __nv_bfloat16* __restrict__ lo,
                                             int i0, int j0, uint32_t sbase,
                                             float acc[2][8][4]) {
    const int tid = threadIdx.x;
    const int lane = tid & 31, wid = tid >> 5;
    const int wm = wid & 3, wn = wid >> 2;
    const int grp = lane >> 3, lr = lane & 7;
    const int NCH = (NSEG * KSRC) / 64;

    // per-thread load slots: 4 x 16B per tile
    int rows[4], cols[4];
    #pragma unroll
    for (int t = 0; t < 4; t++) {
        int c = tid + t * 256;
        rows[t] = c >> 3;
        cols[t] = (c & 7) * 8; // element offset within 64-wide chunk
    }

    // issue loads for chunk kc into stage st
    auto issue = [&](int kc, int st) {
        int gk = kc * 64;
        int seg = gk / KSRC;
        int kk = gk - seg * KSRC;
        const __nv_bfloat16* sa;
        const __nv_bfloat16* sb;
        if (NSEG == 4) {
            sa = (seg >> 1) ? lo : hi;
            sb = (seg & 1) ? lo : hi;
        } else {
            sa = (seg == 2) ? lo : hi;
            sb = (seg == 1) ? lo : hi;
        }
        uint32_t ab = sbase + st * 32768;
        uint32_t bb = ab + 16384;
        #pragma unroll
        for (int t = 0; t < 4; t++) {
            uint32_t sw = SWZ(rows[t] * 128 + cols[t] * 2);
            cp16(ab + sw, sa + (size_t)(i0 + rows[t]) * KSRC + kk + cols[t]);
            cp16(bb + sw, sb + (size_t)(j0 + rows[t]) * KSRC + kk + cols[t]);
        }
        CP_COMMIT();
    };

    issue(0, 0);
    for (int kc = 0; kc < NCH; kc++) {
        int st = kc & 1;
        if (kc + 1 < NCH) { issue(kc + 1, st ^ 1); CP_WAIT1(); }
        else { CP_WAIT0(); }
        __syncthreads();
        uint32_t ab = sbase + st * 32768;
        uint32_t bb = ab + 16384;
        #pragma unroll
        for (int ks = 0; ks < 4; ks++) {
            uint32_t a[2][4], b[4][4];
            #pragma unroll
            for (int mi = 0; mi < 2; mi++) {
                int mrow = wm * 32 + mi * 16 + (grp & 1) * 8 + lr;
                uint32_t addr = ab + SWZ(mrow * 128 + ks * 32 + (grp >> 1) * 16);
                ldsm4(a[mi][0], a[mi][1], a[mi][2], a[mi][3], addr);
            }
            #pragma unroll
            for (int nb = 0; nb < 4; nb++) {
                int nrow = wn * 64 + nb * 16 + (grp & 1) * 8 + lr;
                uint32_t addr = bb + SWZ(nrow * 128 + ks * 32 + (grp >> 1) * 16);
                ldsm4(b[nb][0], b[nb][1], b[nb][2], b[nb][3], addr);
            }
            #pragma unroll
            for (int mi = 0; mi < 2; mi++)
                #pragma unroll
                for (int ni = 0; ni < 8; ni++) {
                    int nb = ni >> 1, h = ni & 1;
                    mma16816(acc[mi][ni], a[mi], b[nb][h], b[nb][h + 2]);
                }
        }
        __syncthreads();
    }
}

// stage warp accumulators into smem C tile (stride CSTR, conflict-free both ways)
__device__ __forceinline__ void stage_c(float* cs, float acc[2][8][4]) {
    const int lane = threadIdx.x & 31, wid = threadIdx.x >> 5;
    const int wm = wid & 3, wn = wid >> 2;
    #pragma unroll
    for (int mi = 0; mi < 2; mi++)
        #pragma unroll
        for (int ni = 0; ni < 8; ni++) {
            int r0 = wm * 32 + mi * 16 + (lane >> 2);
            int c0 = wn * 64 + ni * 8 + (lane & 3) * 2;
            cs[r0 * CSTR + c0] = acc[mi][ni][0];
            cs[r0 * CSTR + c0 + 1] = acc[mi][ni][1];
            cs[(r0 + 8) * CSTR + c0] = acc[mi][ni][2];
            cs[(r0 + 8) * CSTR + c0 + 1] = acc[mi][ni][3];
        }
}

// ---------------- GEMM 1: squared distances (4-segment exact split) -----------
__global__ __launch_bounds__(256, 2) void k_gemm_d2_mma() {
    extern __shared__ char dsm[];
    __shared__ float srow[128], scol[128];
    const int tid = threadIdx.x;
    int bi, bj;
    tri_map(blockIdx.x, bi, bj);
    int i0 = bi * BM, j0 = bj * BM;
    uint32_t sbase = smem_u32(dsm);

    float acc[2][8][4];
    #pragma unroll
    for (int a = 0; a < 2; a++)
        #pragma unroll
        for (int b = 0; b < 8; b++)
            #pragma unroll
            for (int c = 0; c < 4; c++) acc[a][b][c] = 0.f;

    mma_mainloop<D1, 4>(g_ahi, g_alo, i0, j0, sbase, acc);

    float* cs = (float*)dsm;
    stage_c(cs, acc);
    if (tid < 128) { srow[tid] = g_sq[i0 + tid]; scol[tid] = g_sq[j0 + tid]; }
    __syncthreads();

    #pragma unroll 4
    for (int t = 0; t < 64; t++) {
        int e = t * 256 + tid;
        int r = e >> 7, c = e & 127;
        float d2 = fmaxf(srow[r] + scol[c] - 2.0f * cs[r * CSTR + c], 0.0f);
        g_d2[(size_t)(i0 + r) * N + j0 + c] = d2;
    }
    if (bi != bj) {
        #pragma unroll 4
        for (int t = 0; t < 64; t++) {
            int e = t * 256 + tid;
            int r = e >> 7, c = e & 127; // r = j-local row, c = i-local col
            float d2 = fmaxf(srow[c] + scol[r] - 2.0f * cs[c * CSTR + r], 0.0f);
            g_d2[(size_t)(j0 + r) * N + i0 + c] = d2;
        }
    }
}

// ---------------- GEMM 2: cosine + masks + both planes (3-segment split) ------
__global__ __launch_bounds__(256, 2) void k_gemm_out_mma(float* __restrict__ out) {
    extern __shared__ char dsm[];
    __shared__ float rrow[128], rcol[128];
    __shared__ unsigned long long mr[128][2];
    const int tid = threadIdx.x;
    int bi, bj;
    tri_map(blockIdx.x, bi, bj);
    int i0 = bi * BM, j0 = bj * BM;
    uint32_t sbase = smem_u32(dsm);

    float acc[2][8][4];
    #pragma unroll
    for (int a = 0; a < 2; a++)
        #pragma unroll
        for (int b = 0; b < 8; b++)
            #pragma unroll
            for (int c = 0; c < 4; c++) acc[a][b][c] = 0.f;

    mma_mainloop<D2H, 3>(g_bhi, g_blo, i0, j0, sbase, acc);

    float* cs = (float*)dsm;
    stage_c(cs, acc);
    if (tid < 128) { rrow[tid] = g_rn[i0 + tid]; rcol[tid] = g_rn[j0 + tid]; }
    mr[tid >> 1][tid & 1] = g_mask[(size_t)(i0 + (tid >> 1)) * MASKW + (j0 >> 6) + (tid & 1)];
    __syncthreads();

    float asum = (float)g_asum;
    float Nw = 0.5f / asum;                                // (1-ALPHA)/a_sum
    float Nb = 1.0f / ((float)N * (float)N - 2.0f * asum); // 1/(sum(non_anchor)-a_sum)
    const size_t NN = (size_t)N * N;

    #pragma unroll 4
    for (int t = 0; t < 64; t++) {
        int e = t * 256 + tid;
        int r = e >> 7, c = e & 127;
        float C = cs[r * CSTR + c] * rrow[r] * rcol[c];
        unsigned a = (unsigned)((mr[r][c >> 6] >> (c & 63)) & 1ull);
        size_t o = (size_t)(i0 + r) * N + j0 + c;
        out[o] = a ? 0.0f : Nb * C;
        out[NN + o] = a ? Nw * C : 0.0f;
    }
    if (bi != bj) {
        #pragma unroll 4
        for (int t = 0; t < 64; t++) {
            int e = t * 256 + tid;
            int r = e >> 7, c = e & 127; // (j0+r, i0+c)
            float C = cs[c * CSTR + r] * rrow[c] * rcol[r];
            unsigned a = (unsigned)((mr[c][r >> 6] >> (r & 63)) & 1ull);
            size_t o = (size_t)(j0 + r) * N + i0 + c;
            out[o] = a ? 0.0f : Nb * C;
            out[NN + o] = a ? Nw * C : 0.0f;
        }
    }
}

// ---------------- kNN: register bitonic top-16 --------------------------------
__device__ __forceinline__ void ce_asc(unsigned long long& a, unsigned long long& b) {
    unsigned long long lo = a < b ? a : b;
    unsigned long long hi = a < b ? b : a;
    a = lo; b = hi;
}
__device__ __forceinline__ void sort16(unsigned long long k[16]) {
    #pragma unroll
    for (int kk = 2; kk <= 16; kk <<= 1) {
        #pragma unroll
        for (int j = kk >> 1; j > 0; j >>= 1) {
            #pragma unroll
            for (int i = 0; i < 16; i++) {
                int l = i ^ j;
                if (l > i) {
                    if ((i & kk) == 0) ce_asc(k[i], k[l]);
                    else ce_asc(k[l], k[i]);
                }
            }
        }
    }
}
__device__ __forceinline__ void merge_xor(unsigned long long k[16], int off) {
    unsigned long long b[16];
    #pragma unroll
    for (int i = 0; i < 16; i++) b[i] = __shfl_xor_sync(0xFFFFFFFFu, k[15 - i], off);
    #pragma unroll
    for (int i = 0; i < 16; i++) k[i] = k[i] < b[i] ? k[i] : b[i];
    #pragma unroll
    for (int s = 8; s > 0; s >>= 1) {
        #pragma unroll
        for (int i = 0; i < 16; i++)
            if (!(i & s)) ce_asc(k[i], k[i | s]);
    }
}

__global__ __launch_bounds__(256) void k_knn() {
    int row = blockIdx.x, tid = threadIdx.x;
    const float4* dr = (const float4*)(g_d2 + (size_t)row * N);
    unsigned long long k[16];
    #pragma unroll
    for (int r = 0; r < 4; r++) {
        int c4 = tid + r * 256;
        float4 v = dr[c4];
        int cb = c4 * 4;
        k[r * 4 + 0] = ((unsigned long long)__float_as_uint(v.x) << 32) | (unsigned)(cb + 0);
        k[r * 4 + 1] = ((unsigned long long)__float_as_uint(v.y) << 32) | (unsigned)(cb + 1);
        k[r * 4 + 2] = ((unsigned long long)__float_as_uint(v.z) << 32) | (unsigned)(cb + 2);
        k[r * 4 + 3] = ((unsigned long long)__float_as_uint(v.w) << 32) | (unsigned)(cb + 3);
    }
    sort16(k);
    merge_xor(k, 1); merge_xor(k, 2); merge_xor(k, 4); merge_xor(k, 8); merge_xor(k, 16);

    __shared__ unsigned long long lists[8][16];
    if ((tid & 31) == 0) {
        #pragma unroll
        for (int t = 0; t < 16; t++) lists[tid >> 5][t] = k[t];
    }
    __syncthreads();
    if (tid < 32) {
        unsigned long long m[16];
        if (tid < 8) {
            #pragma unroll
            for (int t = 0; t < 16; t++) m[t] = lists[tid][t];
        } else {
            #pragma unroll
            for (int t = 0; t < 16; t++) m[t] = ~0ull;
        }
        merge_xor(m, 1); merge_xor(m, 2); merge_xor(m, 4);
        if (tid == 0) {
            #pragma unroll
            for (int t = 0; t < KNN; t++) {
                unsigned j = (unsigned)m[t];
                atomicOr(&g_mask[(size_t)row * MASKW + (j >> 6)], 1ull << (j & 63));
                atomicOr(&g_mask[(size_t)j * MASKW + (row >> 6)], 1ull << (row & 63));
            }
        }
    }
}

__global__ void k_count() {
    int i = blockIdx.x * blockDim.x + threadIdx.x;
    int cnt = 0;
    const int total = N * MASKW;
    for (; i < total; i += gridDim.x * blockDim.x) cnt += __popcll(g_mask[i]);
    #pragma unroll
    for (int o = 16; o; o >>= 1) cnt += __shfl_down_sync(0xFFFFFFFFu, cnt, o);
    if ((threadIdx.x & 31) == 0 && cnt) atomicAdd(&g_asum, cnt);
}

// ---------------------------------------------------------------------------
extern "C" void kernel_launch(void* const* d_in, const int* in_sizes, int n_in,
                              void* d_out, int out_size) {
    const float* orig = (const float*)d_in[0]; // [4096, 512]
    const float* hid  = (const float*)d_in[1]; // [4096, 1024]
    float* out = (float*)d_out;                // [2, 4096, 4096]

    cudaFuncSetAttribute(k_gemm_d2_mma, cudaFuncAttributeMaxDynamicSharedMemorySize, DYN_SMEM);
    cudaFuncSetAttribute(k_gemm_out_mma, cudaFuncAttributeMaxDynamicSharedMemorySize, DYN_SMEM);

    k_zero<<<256, 256>>>();
    k_split<<<2048, 256>>>(orig, hid);
    k_rowstats<<<1024, 256>>>(orig, hid);
    k_gemm_d2_mma<<<NBLK, 256, DYN_SMEM>>>();
    k_knn<<<N, 256>>>();
    k_count<<<256, 256>>>();
    k_gemm_out_mma<<<NBLK, 256, DYN_SMEM>>>(out);
}

// round 5
// speedup vs baseline: 2.8848x; 1.0131x over previous
#include <cuda_runtime.h>
#include <cuda_bf16.h>
#include <stdint.h>

#define N 4096
#define D1 512
#define D2H 1024
#define KNN 10
#define MASKW (N / 64)
#define BM 128
#define NTILES (N / BM)                    // 32
#define NBLK ((NTILES * (NTILES + 1)) / 2) // 528
#define CSTR 129                           // smem C tile stride (floats)
#define STAGE_B 32768
#define DYN_SMEM (3 * STAGE_B)             // 98304: 3 stages of (A 16K + B 16K)

// ---------------- scratch (device globals; no allocation allowed) ----------
__device__ __align__(16) float g_d2[(size_t)N * N];      // 64 MB
__device__ unsigned long long g_mask[(size_t)N * MASKW]; // 2 MB
__device__ int g_asum;
__device__ float g_sq[N];
__device__ float g_rn[N];
__device__ __align__(16) __nv_bfloat16 g_ahi[(size_t)N * D1];
__device__ __align__(16) __nv_bfloat16 g_alo[(size_t)N * D1];
__device__ __align__(16) __nv_bfloat16 g_bhi[(size_t)N * D2H];
__device__ __align__(16) __nv_bfloat16 g_blo[(size_t)N * D2H];

// ---------------- helpers ----------------------------------------------------
__device__ __forceinline__ uint32_t smem_u32(const void* p) {
    uint32_t a;
    asm("{ .reg .u64 t; cvta.to.shared.u64 t, %1; cvt.u32.u64 %0, t; }" : "=r"(a) : "l"(p));
    return a;
}
#define SWZ(x) ((uint32_t)(x) ^ ((((uint32_t)(x)) >> 3) & 0x70))

__device__ __forceinline__ void cp16(uint32_t s, const void* g) {
    asm volatile("cp.async.cg.shared.global [%0], [%1], 16;" :: "r"(s), "l"(g));
}
#define CP_COMMIT() asm volatile("cp.async.commit_group;" ::: "memory")
#define CP_WAIT0() asm volatile("cp.async.wait_group 0;" ::: "memory")
#define CP_WAIT1() asm volatile("cp.async.wait_group 1;" ::: "memory")

__device__ __forceinline__ void ldsm4(uint32_t& r0, uint32_t& r1, uint32_t& r2, uint32_t& r3,
                                      uint32_t addr) {
    asm volatile("ldmatrix.sync.aligned.m8n8.x4.shared.b16 {%0,%1,%2,%3}, [%4];"
                 : "=r"(r0), "=r"(r1), "=r"(r2), "=r"(r3) : "r"(addr));
}
__device__ __forceinline__ void mma16816(float c[4], const uint32_t a[4],
                                         uint32_t b0, uint32_t b1) {
    asm volatile("mma.sync.aligned.m16n8k16.row.col.f32.bf16.bf16.f32 "
                 "{%0,%1,%2,%3}, {%4,%5,%6,%7}, {%8,%9}, {%0,%1,%2,%3};"
                 : "+f"(c[0]), "+f"(c[1]), "+f"(c[2]), "+f"(c[3])
                 : "r"(a[0]), "r"(a[1]), "r"(a[2]), "r"(a[3]), "r"(b0), "r"(b1));
}

__device__ __forceinline__ void tri_map(int t, int& bi, int& bj) {
    int i = 0, rem = t, span = NTILES;
    while (rem >= span) { rem -= span; i++; span--; }
    bi = i;
    bj = i + rem;
}

// ---------------- setup kernels ------------------------------------------------
__global__ void k_zero() {
    int i = blockIdx.x * blockDim.x + threadIdx.x;
    const int total = N * MASKW;
    for (; i < total; i += gridDim.x * blockDim.x) g_mask[i] = 0ull;
    if (blockIdx.x == 0 && threadIdx.x == 0) g_asum = 0;
}

// fused: bf16 hi/lo split + row sum-of-squares, one warp per row
__global__ __launch_bounds__(256) void k_prep(const float* __restrict__ orig,
                                              const float* __restrict__ hid) {
    int w = blockIdx.x * 8 + (threadIdx.x >> 5);
    int lane = threadIdx.x & 31;
    if (w < N) {
        const float4* src = (const float4*)(orig + (size_t)w * D1);
        uint2* dhi = (uint2*)(g_ahi + (size_t)w * D1);
        uint2* dlo = (uint2*)(g_alo + (size_t)w * D1);
        float s = 0.f;
        #pragma unroll
        for (int ch = 0; ch < D1 / 128; ch++) {
            int c = lane + ch * 32;
            float4 v = src[c];
            s += v.x * v.x + v.y * v.y + v.z * v.z + v.w * v.w;
            __nv_bfloat16 hx = __float2bfloat16(v.x), hy = __float2bfloat16(v.y);
            __nv_bfloat16 hz = __float2bfloat16(v.z), hw = __float2bfloat16(v.w);
            __nv_bfloat162 h0 = {hx, hy}, h1 = {hz, hw};
            __nv_bfloat162 l0 = {__float2bfloat16(v.x - __bfloat162float(hx)),
                                 __float2bfloat16(v.y - __bfloat162float(hy))};
            __nv_bfloat162 l1 = {__float2bfloat16(v.z - __bfloat162float(hz)),
                                 __float2bfloat16(v.w - __bfloat162float(hw))};
            dhi[c] = make_uint2(*(uint32_t*)&h0, *(uint32_t*)&h1);
            dlo[c] = make_uint2(*(uint32_t*)&l0, *(uint32_t*)&l1);
        }
        #pragma unroll
        for (int o = 16; o; o >>= 1) s += __shfl_down_sync(0xFFFFFFFFu, s, o);
        if (lane == 0) g_sq[w] = s;
    } else {
        int r = w - N;
        const float4* src = (const float4*)(hid + (size_t)r * D2H);
        uint2* dhi = (uint2*)(g_bhi + (size_t)r * D2H);
        uint2* dlo = (uint2*)(g_blo + (size_t)r * D2H);
        float s = 0.f;
        #pragma unroll
        for (int ch = 0; ch < D2H / 128; ch++) {
            int c = lane + ch * 32;
            float4 v = src[c];
            s += v.x * v.x + v.y * v.y + v.z * v.z + v.w * v.w;
            __nv_bfloat16 hx = __float2bfloat16(v.x), hy = __float2bfloat16(v.y);
            __nv_bfloat16 hz = __float2bfloat16(v.z), hw = __float2bfloat16(v.w);
            __nv_bfloat162 h0 = {hx, hy}, h1 = {hz, hw};
            __nv_bfloat162 l0 = {__float2bfloat16(v.x - __bfloat162float(hx)),
                                 __float2bfloat16(v.y - __bfloat162float(hy))};
            __nv_bfloat162 l1 = {__float2bfloat16(v.z - __bfloat162float(hz)),
                                 __float2bfloat16(v.w - __bfloat162float(hw))};
            dhi[c] = make_uint2(*(uint32_t*)&h0, *(uint32_t*)&h1);
            dlo[c] = make_uint2(*(uint32_t*)&l0, *(uint32_t*)&l1);
        }
        #pragma unroll
        for (int o = 16; o; o >>= 1) s += __shfl_down_sync(0xFFFFFFFFu, s, o);
        if (lane == 0) g_rn[r] = 1.0f / fmaxf(sqrtf(s), 1e-12f);
    }
}

// ---------------- HMMA mainloop: 3-stage cp.async, 1 barrier/chunk --------------
// NSEG==4: seg s: A=(s>>1?lo:hi), B=(s&1?lo:hi)   [exact product set]
// NSEG==3: seg0 hi*hi, seg1 hi*lo, seg2 lo*hi     [drops lo*lo]
template <int KSRC, int NSEG>
__device__ __forceinline__ void mma_mainloop(const __nv_bfloat16* __restrict__ hi,
                                             const __nv_bfloat16* __restrict__ lo,
                                             int i0, int j0, uint32_t sbase,
                                             float acc[2][8][4]) {
    const int tid = threadIdx.x;
    const int lane = tid & 31, wid = tid >> 5;
    const int wm = wid & 3, wn = wid >> 2;
    const int grp = lane >> 3, lr = lane & 7;
    const int NCH = (NSEG * KSRC) / 64;

    int rows[4], cols[4];
    #pragma unroll
    for (int t = 0; t < 4; t++) {
        int c = tid + t * 256;
        rows[t] = c >> 3;
        cols[t] = (c & 7) * 8;
    }

    auto issue = [&](int kc, int st) {
        int gk = kc * 64;
        int seg = gk / KSRC;
        int kk = gk - seg * KSRC;
        const __nv_bfloat16* sa;
        const __nv_bfloat16* sb;
        if (NSEG == 4) {
            sa = (seg >> 1) ? lo : hi;
            sb = (seg & 1) ? lo : hi;
        } else {
            sa = (seg == 2) ? lo : hi;
            sb = (seg == 1) ? lo : hi;
        }
        uint32_t ab = sbase + st * STAGE_B;
        uint32_t bb = ab + 16384;
        #pragma unroll
        for (int t = 0; t < 4; t++) {
            uint32_t sw = SWZ(rows[t] * 128 + cols[t] * 2);
            cp16(ab + sw, sa + (size_t)(i0 + rows[t]) * KSRC + kk + cols[t]);
            cp16(bb + sw, sb + (size_t)(j0 + rows[t]) * KSRC + kk + cols[t]);
        }
        CP_COMMIT();
    };

    issue(0, 0);
    issue(1, 1);
    int st = 0;
    for (int kc = 0; kc < NCH; kc++) {
        if (kc + 1 < NCH) CP_WAIT1(); else CP_WAIT0();
        __syncthreads();
        if (kc + 2 < NCH) {
            int st2 = st + 2; if (st2 >= 3) st2 -= 3;
            issue(kc + 2, st2);
        }
        uint32_t ab = sbase + st * STAGE_B;
        uint32_t bb = ab + 16384;
        #pragma unroll
        for (int ks = 0; ks < 4; ks++) {
            uint32_t a[2][4], b[4][4];
            #pragma unroll
            for (int mi = 0; mi < 2; mi++) {
                int mrow = wm * 32 + mi * 16 + (grp & 1) * 8 + lr;
                uint32_t addr = ab + SWZ(mrow * 128 + ks * 32 + (grp >> 1) * 16);
                ldsm4(a[mi][0], a[mi][1], a[mi][2], a[mi][3], addr);
            }
            #pragma unroll
            for (int nb = 0; nb < 4; nb++) {
                int nrow = wn * 64 + nb * 16 + (grp & 1) * 8 + lr;
                uint32_t addr = bb + SWZ(nrow * 128 + ks * 32 + (grp >> 1) * 16);
                ldsm4(b[nb][0], b[nb][1], b[nb][2], b[nb][3], addr);
            }
            #pragma unroll
            for (int mi = 0; mi < 2; mi++)
                #pragma unroll
                for (int ni = 0; ni < 8; ni++) {
                    int nb = ni >> 1, h = ni & 1;
                    mma16816(acc[mi][ni], a[mi], b[nb][h], b[nb][h + 2]);
                }
        }
        if (++st == 3) st = 0;
    }
    __syncthreads();
}

__device__ __forceinline__ void stage_c(float* cs, float acc[2][8][4]) {
    const int lane = threadIdx.x & 31, wid = threadIdx.x >> 5;
    const int wm = wid & 3, wn = wid >> 2;
    #pragma unroll
    for (int mi = 0; mi < 2; mi++)
        #pragma unroll
        for (int ni = 0; ni < 8; ni++) {
            int r0 = wm * 32 + mi * 16 + (lane >> 2);
            int c0 = wn * 64 + ni * 8 + (lane & 3) * 2;
            cs[r0 * CSTR + c0] = acc[mi][ni][0];
            cs[r0 * CSTR + c0 + 1] = acc[mi][ni][1];
            cs[(r0 + 8) * CSTR + c0] = acc[mi][ni][2];
            cs[(r0 + 8) * CSTR + c0 + 1] = acc[mi][ni][3];
        }
}

// ---------------- GEMM 1: squared distances (4-segment exact split) ------------
__global__ __launch_bounds__(256, 2) void k_gemm_d2_mma() {
    extern __shared__ char dsm[];
    __shared__ float srow[128], scol[128];
    const int tid = threadIdx.x;
    int bi, bj;
    tri_map(blockIdx.x, bi, bj);
    int i0 = bi * BM, j0 = bj * BM;
    uint32_t sbase = smem_u32(dsm);

    float acc[2][8][4];
    #pragma unroll
    for (int a = 0; a < 2; a++)
        #pragma unroll
        for (int b = 0; b < 8; b++)
            #pragma unroll
            for (int c = 0; c < 4; c++) acc[a][b][c] = 0.f;

    mma_mainloop<D1, 4>(g_ahi, g_alo, i0, j0, sbase, acc);

    float* cs = (float*)dsm;
    stage_c(cs, acc);
    if (tid < 128) { srow[tid] = g_sq[i0 + tid]; scol[tid] = g_sq[j0 + tid]; }
    __syncthreads();

    #pragma unroll 4
    for (int t = 0; t < 64; t++) {
        int e = t * 256 + tid;
        int r = e >> 7, c = e & 127;
        float d2 = fmaxf(srow[r] + scol[c] - 2.0f * cs[r * CSTR + c], 0.0f);
        g_d2[(size_t)(i0 + r) * N + j0 + c] = d2;
    }
    if (bi != bj) {
        #pragma unroll 4
        for (int t = 0; t < 64; t++) {
            int e = t * 256 + tid;
            int r = e >> 7, c = e & 127;
            float d2 = fmaxf(srow[c] + scol[r] - 2.0f * cs[c * CSTR + r], 0.0f);
            g_d2[(size_t)(j0 + r) * N + i0 + c] = d2;
        }
    }
}

// ---------------- GEMM 2: cosine + masks + both planes (3-segment split) -------
__global__ __launch_bounds__(256, 2) void k_gemm_out_mma(float* __restrict__ out) {
    extern __shared__ char dsm[];
    __shared__ float rrow[128], rcol[128];
    __shared__ unsigned long long mr[128][2];
    const int tid = threadIdx.x;
    int bi, bj;
    tri_map(blockIdx.x, bi, bj);
    int i0 = bi * BM, j0 = bj * BM;
    uint32_t sbase = smem_u32(dsm);

    float acc[2][8][4];
    #pragma unroll
    for (int a = 0; a < 2; a++)
        #pragma unroll
        for (int b = 0; b < 8; b++)
            #pragma unroll
            for (int c = 0; c < 4; c++) acc[a][b][c] = 0.f;

    mma_mainloop<D2H, 3>(g_bhi, g_blo, i0, j0, sbase, acc);

    float* cs = (float*)dsm;
    stage_c(cs, acc);
    if (tid < 128) { rrow[tid] = g_rn[i0 + tid]; rcol[tid] = g_rn[j0 + tid]; }
    mr[tid >> 1][tid & 1] = g_mask[(size_t)(i0 + (tid >> 1)) * MASKW + (j0 >> 6) + (tid & 1)];
    __syncthreads();

    float asum = (float)g_asum;
    float Nw = 0.5f / asum;
    float Nb = 1.0f / ((float)N * (float)N - 2.0f * asum);
    const size_t NN = (size_t)N * N;

    #pragma unroll 4
    for (int t = 0; t < 64; t++) {
        int e = t * 256 + tid;
        int r = e >> 7, c = e & 127;
        float C = cs[r * CSTR + c] * rrow[r] * rcol[c];
        unsigned a = (unsigned)((mr[r][c >> 6] >> (c & 63)) & 1ull);
        size_t o = (size_t)(i0 + r) * N + j0 + c;
        out[o] = a ? 0.0f : Nb * C;
        out[NN + o] = a ? Nw * C : 0.0f;
    }
    if (bi != bj) {
        #pragma unroll 4
        for (int t = 0; t < 64; t++) {
            int e = t * 256 + tid;
            int r = e >> 7, c = e & 127;
            float C = cs[c * CSTR + r] * rrow[c] * rcol[r];
            unsigned a = (unsigned)((mr[c][r >> 6] >> (r & 63)) & 1ull);
            size_t o = (size_t)(j0 + r) * N + i0 + c;
            out[o] = a ? 0.0f : Nb * C;
            out[NN + o] = a ? Nw * C : 0.0f;
        }
    }
}

// ---------------- kNN: register bitonic top-16 --------------------------------
__device__ __forceinline__ void ce_asc(unsigned long long& a, unsigned long long& b) {
    unsigned long long lo = a < b ? a : b;
    unsigned long long hi = a < b ? b : a;
    a = lo; b = hi;
}
__device__ __forceinline__ void sort16(unsigned long long k[16]) {
    #pragma unroll
    for (int kk = 2; kk <= 16; kk <<= 1) {
        #pragma unroll
        for (int j = kk >> 1; j > 0; j >>= 1) {
            #pragma unroll
            for (int i = 0; i < 16; i++) {
                int l = i ^ j;
                if (l > i) {
                    if ((i & kk) == 0) ce_asc(k[i], k[l]);
                    else ce_asc(k[l], k[i]);
                }
            }
        }
    }
}
__device__ __forceinline__ void merge_xor(unsigned long long k[16], int off) {
    unsigned long long b[16];
    #pragma unroll
    for (int i = 0; i < 16; i++) b[i] = __shfl_xor_sync(0xFFFFFFFFu, k[15 - i], off);
    #pragma unroll
    for (int i = 0; i < 16; i++) k[i] = k[i] < b[i] ? k[i] : b[i];
    #pragma unroll
    for (int s = 8; s > 0; s >>= 1) {
        #pragma unroll
        for (int i = 0; i < 16; i++)
            if (!(i & s)) ce_asc(k[i], k[i | s]);
    }
}

__global__ __launch_bounds__(256) void k_knn() {
    int row = blockIdx.x, tid = threadIdx.x;
    const float4* dr = (const float4*)(g_d2 + (size_t)row * N);
    unsigned long long k[16];
    #pragma unroll
    for (int r = 0; r < 4; r++) {
        int c4 = tid + r * 256;
        float4 v = dr[c4];
        int cb = c4 * 4;
        k[r * 4 + 0] = ((unsigned long long)__float_as_uint(v.x) << 32) | (unsigned)(cb + 0);
        k[r * 4 + 1] = ((unsigned long long)__float_as_uint(v.y) << 32) | (unsigned)(cb + 1);
        k[r * 4 + 2] = ((unsigned long long)__float_as_uint(v.z) << 32) | (unsigned)(cb + 2);
        k[r * 4 + 3] = ((unsigned long long)__float_as_uint(v.w) << 32) | (unsigned)(cb + 3);
    }
    sort16(k);
    merge_xor(k, 1); merge_xor(k, 2); merge_xor(k, 4); merge_xor(k, 8); merge_xor(k, 16);

    __shared__ unsigned long long lists[8][16];
    if ((tid & 31) == 0) {
        #pragma unroll
        for (int t = 0; t < 16; t++) lists[tid >> 5][t] = k[t];
    }
    __syncthreads();
    if (tid < 32) {
        unsigned long long m[16];
        if (tid < 8) {
            #pragma unroll
            for (int t = 0; t < 16; t++) m[t] = lists[tid][t];
        } else {
            #pragma unroll
            for (int t = 0; t < 16; t++) m[t] = ~0ull;
        }
        merge_xor(m, 1); merge_xor(m, 2); merge_xor(m, 4);
        if (tid == 0) {
            #pragma unroll
            for (int t = 0; t < KNN; t++) {
                unsigned j = (unsigned)m[t];
                atomicOr(&g_mask[(size_t)row * MASKW + (j >> 6)], 1ull << (j & 63));
                atomicOr(&g_mask[(size_t)j * MASKW + (row >> 6)], 1ull << (row & 63));
            }
        }
    }
}

__global__ void k_count() {
    int i = blockIdx.x * blockDim.x + threadIdx.x;
    int cnt = 0;
    const int total = N * MASKW;
    for (; i < total; i += gridDim.x * blockDim.x) cnt += __popcll(g_mask[i]);
    #pragma unroll
    for (int o = 16; o; o >>= 1) cnt += __shfl_down_sync(0xFFFFFFFFu, cnt, o);
    if ((threadIdx.x & 31) == 0 && cnt) atomicAdd(&g_asum, cnt);
}

// ---------------------------------------------------------------------------
extern "C" void kernel_launch(void* const* d_in, const int* in_sizes, int n_in,
                              void* d_out, int out_size) {
    const float* orig = (const float*)d_in[0]; // [4096, 512]
    const float* hid  = (const float*)d_in[1]; // [4096, 1024]
    float* out = (float*)d_out;                // [2, 4096, 4096]

    cudaFuncSetAttribute(k_gemm_d2_mma, cudaFuncAttributeMaxDynamicSharedMemorySize, DYN_SMEM);
    cudaFuncSetAttribute(k_gemm_out_mma, cudaFuncAttributeMaxDynamicSharedMemorySize, DYN_SMEM);

    k_zero<<<256, 256>>>();
    k_prep<<<1024, 256>>>(orig, hid);
    k_gemm_d2_mma<<<NBLK, 256, DYN_SMEM>>>();
    k_knn<<<N, 256>>>();
    k_count<<<256, 256>>>();
    k_gemm_out_mma<<<NBLK, 256, DYN_SMEM>>>(out);
}

// round 6
// speedup vs baseline: 3.5694x; 1.2373x over previous
#include <cuda_runtime.h>
#include <cuda_bf16.h>
#include <stdint.h>

#define N 4096
#define D1 512
#define D2H 1024
#define KNN 10
#define MASKW (N / 64)
#define BM 128
#define NTILES (N / BM)                    // 32
#define NBLK ((NTILES * (NTILES + 1)) / 2) // 528
#define CSTR 129                           // smem C tile stride (floats)
#define STAGE_B 32768
#define DYN_SMEM (3 * STAGE_B)             // 98304: 3 stages of (A 16K + B 16K)

// ---------------- scratch (device globals; no allocation allowed) ----------
__device__ __align__(16) float g_d2[(size_t)N * N];      // 64 MB
__device__ unsigned long long g_mask[(size_t)N * MASKW]; // 2 MB
__device__ int g_asum;
__device__ float g_sq[N];
__device__ float g_rn[N];
__device__ __align__(16) __nv_bfloat16 g_ahi[(size_t)N * D1];
__device__ __align__(16) __nv_bfloat16 g_alo[(size_t)N * D1];
__device__ __align__(16) __nv_bfloat16 g_bhi[(size_t)N * D2H];
__device__ __align__(16) __nv_bfloat16 g_blo[(size_t)N * D2H];

// ---------------- helpers ----------------------------------------------------
__device__ __forceinline__ uint32_t smem_u32(const void* p) {
    uint32_t a;
    asm("{ .reg .u64 t; cvta.to.shared.u64 t, %1; cvt.u32.u64 %0, t; }" : "=r"(a) : "l"(p));
    return a;
}
#define SWZ(x) ((uint32_t)(x) ^ ((((uint32_t)(x)) >> 3) & 0x70))

__device__ __forceinline__ void cp16(uint32_t s, const void* g) {
    asm volatile("cp.async.cg.shared.global [%0], [%1], 16;" :: "r"(s), "l"(g));
}
#define CP_COMMIT() asm volatile("cp.async.commit_group;" ::: "memory")
#define CP_WAIT0() asm volatile("cp.async.wait_group 0;" ::: "memory")
#define CP_WAIT1() asm volatile("cp.async.wait_group 1;" ::: "memory")

__device__ __forceinline__ void ldsm4(uint32_t& r0, uint32_t& r1, uint32_t& r2, uint32_t& r3,
                                      uint32_t addr) {
    asm volatile("ldmatrix.sync.aligned.m8n8.x4.shared.b16 {%0,%1,%2,%3}, [%4];"
                 : "=r"(r0), "=r"(r1), "=r"(r2), "=r"(r3) : "r"(addr));
}
__device__ __forceinline__ void mma16816(float c[4], const uint32_t a[4],
                                         uint32_t b0, uint32_t b1) {
    asm volatile("mma.sync.aligned.m16n8k16.row.col.f32.bf16.bf16.f32 "
                 "{%0,%1,%2,%3}, {%4,%5,%6,%7}, {%8,%9}, {%0,%1,%2,%3};"
                 : "+f"(c[0]), "+f"(c[1]), "+f"(c[2]), "+f"(c[3])
                 : "r"(a[0]), "r"(a[1]), "r"(a[2]), "r"(a[3]), "r"(b0), "r"(b1));
}

__device__ __forceinline__ void tri_map(int t, int& bi, int& bj) {
    int i = 0, rem = t, span = NTILES;
    while (rem >= span) { rem -= span; i++; span--; }
    bi = i;
    bj = i + rem;
}

// ---------------- setup kernels ------------------------------------------------
__global__ void k_zero() {
    int i = blockIdx.x * blockDim.x + threadIdx.x;
    const int total = N * MASKW;
    for (; i < total; i += gridDim.x * blockDim.x) g_mask[i] = 0ull;
    if (blockIdx.x == 0 && threadIdx.x == 0) g_asum = 0;
}

// fused: bf16 hi/lo split + row sum-of-squares, one warp per row
__global__ __launch_bounds__(256) void k_prep(const float* __restrict__ orig,
                                              const float* __restrict__ hid) {
    int w = blockIdx.x * 8 + (threadIdx.x >> 5);
    int lane = threadIdx.x & 31;
    if (w < N) {
        const float4* src = (const float4*)(orig + (size_t)w * D1);
        uint2* dhi = (uint2*)(g_ahi + (size_t)w * D1);
        uint2* dlo = (uint2*)(g_alo + (size_t)w * D1);
        float s = 0.f;
        #pragma unroll
        for (int ch = 0; ch < D1 / 128; ch++) {
            int c = lane + ch * 32;
            float4 v = src[c];
            s += v.x * v.x + v.y * v.y + v.z * v.z + v.w * v.w;
            __nv_bfloat16 hx = __float2bfloat16(v.x), hy = __float2bfloat16(v.y);
            __nv_bfloat16 hz = __float2bfloat16(v.z), hw = __float2bfloat16(v.w);
            __nv_bfloat162 h0 = {hx, hy}, h1 = {hz, hw};
            __nv_bfloat162 l0 = {__float2bfloat16(v.x - __bfloat162float(hx)),
                                 __float2bfloat16(v.y - __bfloat162float(hy))};
            __nv_bfloat162 l1 = {__float2bfloat16(v.z - __bfloat162float(hz)),
                                 __float2bfloat16(v.w - __bfloat162float(hw))};
            dhi[c] = make_uint2(*(uint32_t*)&h0, *(uint32_t*)&h1);
            dlo[c] = make_uint2(*(uint32_t*)&l0, *(uint32_t*)&l1);
        }
        #pragma unroll
        for (int o = 16; o; o >>= 1) s += __shfl_down_sync(0xFFFFFFFFu, s, o);
        if (lane == 0) g_sq[w] = s;
    } else {
        int r = w - N;
        const float4* src = (const float4*)(hid + (size_t)r * D2H);
        uint2* dhi = (uint2*)(g_bhi + (size_t)r * D2H);
        uint2* dlo = (uint2*)(g_blo + (size_t)r * D2H);
        float s = 0.f;
        #pragma unroll
        for (int ch = 0; ch < D2H / 128; ch++) {
            int c = lane + ch * 32;
            float4 v = src[c];
            s += v.x * v.x + v.y * v.y + v.z * v.z + v.w * v.w;
            __nv_bfloat16 hx = __float2bfloat16(v.x), hy = __float2bfloat16(v.y);
            __nv_bfloat16 hz = __float2bfloat16(v.z), hw = __float2bfloat16(v.w);
            __nv_bfloat162 h0 = {hx, hy}, h1 = {hz, hw};
            __nv_bfloat162 l0 = {__float2bfloat16(v.x - __bfloat162float(hx)),
                                 __float2bfloat16(v.y - __bfloat162float(hy))};
            __nv_bfloat162 l1 = {__float2bfloat16(v.z - __bfloat162float(hz)),
                                 __float2bfloat16(v.w - __bfloat162float(hw))};
            dhi[c] = make_uint2(*(uint32_t*)&h0, *(uint32_t*)&h1);
            dlo[c] = make_uint2(*(uint32_t*)&l0, *(uint32_t*)&l1);
        }
        #pragma unroll
        for (int o = 16; o; o >>= 1) s += __shfl_down_sync(0xFFFFFFFFu, s, o);
        if (lane == 0) g_rn[r] = 1.0f / fmaxf(sqrtf(s), 1e-12f);
    }
}

// ---------------- HMMA mainloop: 3-stage cp.async, 1 barrier/chunk --------------
// NSEG==4: seg s: A=(s>>1?lo:hi), B=(s&1?lo:hi)   [exact product set]
// NSEG==3: seg0 hi*hi, seg1 hi*lo, seg2 lo*hi     [drops lo*lo]
template <int KSRC, int NSEG>
__device__ __forceinline__ void mma_mainloop(const __nv_bfloat16* __restrict__ hi,
                                             const __nv_bfloat16* __restrict__ lo,
                                             int i0, int j0, uint32_t sbase,
                                             float acc[2][8][4]) {
    const int tid = threadIdx.x;
    const int lane = tid & 31, wid = tid >> 5;
    const int wm = wid & 3, wn = wid >> 2;
    const int grp = lane >> 3, lr = lane & 7;
    const int NCH = (NSEG * KSRC) / 64;

    int rows[4], cols[4];
    #pragma unroll
    for (int t = 0; t < 4; t++) {
        int c = tid + t * 256;
        rows[t] = c >> 3;
        cols[t] = (c & 7) * 8;
    }

    auto issue = [&](int kc, int st) {
        int gk = kc * 64;
        int seg = gk / KSRC;
        int kk = gk - seg * KSRC;
        const __nv_bfloat16* sa;
        const __nv_bfloat16* sb;
        if (NSEG == 4) {
            sa = (seg >> 1) ? lo : hi;
            sb = (seg & 1) ? lo : hi;
        } else {
            sa = (seg == 2) ? lo : hi;
            sb = (seg == 1) ? lo : hi;
        }
        uint32_t ab = sbase + st * STAGE_B;
        uint32_t bb = ab + 16384;
        #pragma unroll
        for (int t = 0; t < 4; t++) {
            uint32_t sw = SWZ(rows[t] * 128 + cols[t] * 2);
            cp16(ab + sw, sa + (size_t)(i0 + rows[t]) * KSRC + kk + cols[t]);
            cp16(bb + sw, sb + (size_t)(j0 + rows[t]) * KSRC + kk + cols[t]);
        }
        CP_COMMIT();
    };

    issue(0, 0);
    issue(1, 1);
    int st = 0;
    for (int kc = 0; kc < NCH; kc++) {
        if (kc + 1 < NCH) CP_WAIT1(); else CP_WAIT0();
        __syncthreads();
        if (kc + 2 < NCH) {
            int st2 = st + 2; if (st2 >= 3) st2 -= 3;
            issue(kc + 2, st2);
        }
        uint32_t ab = sbase + st * STAGE_B;
        uint32_t bb = ab + 16384;
        #pragma unroll
        for (int ks = 0; ks < 4; ks++) {
            uint32_t a[2][4], b[4][4];
            #pragma unroll
            for (int mi = 0; mi < 2; mi++) {
                int mrow = wm * 32 + mi * 16 + (grp & 1) * 8 + lr;
                uint32_t addr = ab + SWZ(mrow * 128 + ks * 32 + (grp >> 1) * 16);
                ldsm4(a[mi][0], a[mi][1], a[mi][2], a[mi][3], addr);
            }
            #pragma unroll
            for (int nb = 0; nb < 4; nb++) {
                int nrow = wn * 64 + nb * 16 + (grp & 1) * 8 + lr;
                uint32_t addr = bb + SWZ(nrow * 128 + ks * 32 + (grp >> 1) * 16);
                ldsm4(b[nb][0], b[nb][1], b[nb][2], b[nb][3], addr);
            }
            #pragma unroll
            for (int mi = 0; mi < 2; mi++)
                #pragma unroll
                for (int ni = 0; ni < 8; ni++) {
                    int nb = ni >> 1, h = ni & 1;
                    mma16816(acc[mi][ni], a[mi], b[nb][h], b[nb][h + 2]);
                }
        }
        if (++st == 3) st = 0;
    }
    __syncthreads();
}

__device__ __forceinline__ void stage_c(float* cs, float acc[2][8][4]) {
    const int lane = threadIdx.x & 31, wid = threadIdx.x >> 5;
    const int wm = wid & 3, wn = wid >> 2;
    #pragma unroll
    for (int mi = 0; mi < 2; mi++)
        #pragma unroll
        for (int ni = 0; ni < 8; ni++) {
            int r0 = wm * 32 + mi * 16 + (lane >> 2);
            int c0 = wn * 64 + ni * 8 + (lane & 3) * 2;
            cs[r0 * CSTR + c0] = acc[mi][ni][0];
            cs[r0 * CSTR + c0 + 1] = acc[mi][ni][1];
            cs[(r0 + 8) * CSTR + c0] = acc[mi][ni][2];
            cs[(r0 + 8) * CSTR + c0 + 1] = acc[mi][ni][3];
        }
}

// ---------------- GEMM 1: squared distances (4-segment exact split) ------------
__global__ __launch_bounds__(256, 2) void k_gemm_d2_mma() {
    extern __shared__ char dsm[];
    __shared__ float srow[128], scol[128];
    const int tid = threadIdx.x;
    int bi, bj;
    tri_map(blockIdx.x, bi, bj);
    int i0 = bi * BM, j0 = bj * BM;
    uint32_t sbase = smem_u32(dsm);

    float acc[2][8][4];
    #pragma unroll
    for (int a = 0; a < 2; a++)
        #pragma unroll
        for (int b = 0; b < 8; b++)
            #pragma unroll
            for (int c = 0; c < 4; c++) acc[a][b][c] = 0.f;

    mma_mainloop<D1, 4>(g_ahi, g_alo, i0, j0, sbase, acc);

    float* cs = (float*)dsm;
    stage_c(cs, acc);
    if (tid < 128) { srow[tid] = g_sq[i0 + tid]; scol[tid] = g_sq[j0 + tid]; }
    __syncthreads();

    #pragma unroll 4
    for (int t = 0; t < 64; t++) {
        int e = t * 256 + tid;
        int r = e >> 7, c = e & 127;
        float d2 = fmaxf(srow[r] + scol[c] - 2.0f * cs[r * CSTR + c], 0.0f);
        g_d2[(size_t)(i0 + r) * N + j0 + c] = d2;
    }
    if (bi != bj) {
        #pragma unroll 4
        for (int t = 0; t < 64; t++) {
            int e = t * 256 + tid;
            int r = e >> 7, c = e & 127;
            float d2 = fmaxf(srow[c] + scol[r] - 2.0f * cs[c * CSTR + r], 0.0f);
            g_d2[(size_t)(j0 + r) * N + i0 + c] = d2;
        }
    }
}

// ---------------- GEMM 2: cosine + masks + both planes (3-segment split) -------
__global__ __launch_bounds__(256, 2) void k_gemm_out_mma(float* __restrict__ out) {
    extern __shared__ char dsm[];
    __shared__ float rrow[128], rcol[128];
    __shared__ unsigned long long mr[128][2];
    const int tid = threadIdx.x;
    int bi, bj;
    tri_map(blockIdx.x, bi, bj);
    int i0 = bi * BM, j0 = bj * BM;
    uint32_t sbase = smem_u32(dsm);

    float acc[2][8][4];
    #pragma unroll
    for (int a = 0; a < 2; a++)
        #pragma unroll
        for (int b = 0; b < 8; b++)
            #pragma unroll
            for (int c = 0; c < 4; c++) acc[a][b][c] = 0.f;

    mma_mainloop<D2H, 3>(g_bhi, g_blo, i0, j0, sbase, acc);

    float* cs = (float*)dsm;
    stage_c(cs, acc);
    if (tid < 128) { rrow[tid] = g_rn[i0 + tid]; rcol[tid] = g_rn[j0 + tid]; }
    mr[tid >> 1][tid & 1] = g_mask[(size_t)(i0 + (tid >> 1)) * MASKW + (j0 >> 6) + (tid & 1)];
    __syncthreads();

    float asum = (float)g_asum;
    float Nw = 0.5f / asum;
    float Nb = 1.0f / ((float)N * (float)N - 2.0f * asum);
    const size_t NN = (size_t)N * N;

    #pragma unroll 4
    for (int t = 0; t < 64; t++) {
        int e = t * 256 + tid;
        int r = e >> 7, c = e & 127;
        float C = cs[r * CSTR + c] * rrow[r] * rcol[c];
        unsigned a = (unsigned)((mr[r][c >> 6] >> (c & 63)) & 1ull);
        size_t o = (size_t)(i0 + r) * N + j0 + c;
        out[o] = a ? 0.0f : Nb * C;
        out[NN + o] = a ? Nw * C : 0.0f;
    }
    if (bi != bj) {
        #pragma unroll 4
        for (int t = 0; t < 64; t++) {
            int e = t * 256 + tid;
            int r = e >> 7, c = e & 127;
            float C = cs[c * CSTR + r] * rrow[c] * rcol[r];
            unsigned a = (unsigned)((mr[c][r >> 6] >> (r & 63)) & 1ull);
            size_t o = (size_t)(j0 + r) * N + i0 + c;
            out[o] = a ? 0.0f : Nb * C;
            out[NN + o] = a ? Nw * C : 0.0f;
        }
    }
}

// ---------------- kNN: f32 bitonic threshold + exact candidate select ----------
__device__ __forceinline__ void cef(float& a, float& b) {
    float lo = fminf(a, b), hi = fmaxf(a, b);
    a = lo; b = hi;
}
__device__ __forceinline__ void sortf16(float k[16]) {
    #pragma unroll
    for (int kk = 2; kk <= 16; kk <<= 1) {
        #pragma unroll
        for (int j = kk >> 1; j > 0; j >>= 1) {
            #pragma unroll
            for (int i = 0; i < 16; i++) {
                int l = i ^ j;
                if (l > i) {
                    if ((i & kk) == 0) cef(k[i], k[l]);
                    else cef(k[l], k[i]);
                }
            }
        }
    }
}
__device__ __forceinline__ void mergef_xor(float k[16], int off) {
    float b[16];
    #pragma unroll
    for (int i = 0; i < 16; i++) b[i] = __shfl_xor_sync(0xFFFFFFFFu, k[15 - i], off);
    #pragma unroll
    for (int i = 0; i < 16; i++) k[i] = fminf(k[i], b[i]);
    #pragma unroll
    for (int s = 8; s > 0; s >>= 1) {
        #pragma unroll
        for (int i = 0; i < 16; i++)
            if (!(i & s)) cef(k[i], k[i | s]);
    }
}

__global__ __launch_bounds__(256) void k_knn() {
    int row = blockIdx.x, tid = threadIdx.x;
    int lane = tid & 31, wid = tid >> 5;
    const float4* dr = (const float4*)(g_d2 + (size_t)row * N);

    float4 q[4];
    #pragma unroll
    for (int r = 0; r < 4; r++) q[r] = dr[tid + r * 256];

    float s[16];
    #pragma unroll
    for (int r = 0; r < 4; r++) {
        s[r * 4 + 0] = q[r].x; s[r * 4 + 1] = q[r].y;
        s[r * 4 + 2] = q[r].z; s[r * 4 + 3] = q[r].w;
    }
    sortf16(s);
    mergef_xor(s, 1); mergef_xor(s, 2); mergef_xor(s, 4);
    mergef_xor(s, 8); mergef_xor(s, 16);

    __shared__ float lists[8][16];
    __shared__ float shT;
    __shared__ int cnt;
    __shared__ unsigned long long cand[64];
    if (lane == 0) {
        #pragma unroll
        for (int t = 0; t < 16; t++) lists[wid][t] = s[t];
    }
    if (tid == 0) cnt = 0;
    __syncthreads();

    if (tid < 32) {
        float m[16];
        if (lane < 8) {
            #pragma unroll
            for (int t = 0; t < 16; t++) m[t] = lists[lane][t];
        } else {
            #pragma unroll
            for (int t = 0; t < 16; t++) m[t] = 3.4e38f;
        }
        mergef_xor(m, 1); mergef_xor(m, 2); mergef_xor(m, 4);
        if (lane == 0) shT = m[KNN - 1]; // 10th smallest value
    }
    __syncthreads();

    float T = shT;
    #pragma unroll
    for (int r = 0; r < 4; r++) {
        const float* qe = (const float*)&q[r];
        #pragma unroll
        for (int e = 0; e < 4; e++) {
            float val = qe[e];
            if (val <= T) {
                int p = atomicAdd(&cnt, 1);
                if (p < 64) {
                    unsigned col = (unsigned)((tid + r * 256) * 4 + e);
                    cand[p] = ((unsigned long long)__float_as_uint(val) << 32) | col;
                }
            }
        }
    }
    __syncthreads();

    if (tid == 0) {
        int m = cnt < 64 ? cnt : 64;
        // pick the KNN smallest (value, col) keys — exact reference tie-break
        for (int t = 0; t < KNN; t++) {
            int best = t;
            for (int u = t + 1; u < m; u++)
                if (cand[u] < cand[best]) best = u;
            unsigned long long tmp = cand[best];
            cand[best] = cand[t]; cand[t] = tmp;
            unsigned j = (unsigned)tmp;
            atomicOr(&g_mask[(size_t)row * MASKW + (j >> 6)], 1ull << (j & 63));
            atomicOr(&g_mask[(size_t)j * MASKW + (row >> 6)], 1ull << (row & 63));
        }
    }
}

__global__ void k_count() {
    int i = blockIdx.x * blockDim.x + threadIdx.x;
    int cnt = 0;
    const int total = N * MASKW;
    for (; i < total; i += gridDim.x * blockDim.x) cnt += __popcll(g_mask[i]);
    #pragma unroll
    for (int o = 16; o; o >>= 1) cnt += __shfl_down_sync(0xFFFFFFFFu, cnt, o);
    if ((threadIdx.x & 31) == 0 && cnt) atomicAdd(&g_asum, cnt);
}

// ---------------------------------------------------------------------------
extern "C" void kernel_launch(void* const* d_in, const int* in_sizes, int n_in,
                              void* d_out, int out_size) {
    const float* orig = (const float*)d_in[0]; // [4096, 512]
    const float* hid  = (const float*)d_in[1]; // [4096, 1024]
    float* out = (float*)d_out;                // [2, 4096, 4096]

    cudaFuncSetAttribute(k_gemm_d2_mma, cudaFuncAttributeMaxDynamicSharedMemorySize, DYN_SMEM);
    cudaFuncSetAttribute(k_gemm_out_mma, cudaFuncAttributeMaxDynamicSharedMemorySize, DYN_SMEM);

    k_zero<<<256, 256>>>();
    k_prep<<<1024, 256>>>(orig, hid);
    k_gemm_d2_mma<<<NBLK, 256, DYN_SMEM>>>();
    k_knn<<<N, 256>>>();
    k_count<<<256, 256>>>();
    k_gemm_out_mma<<<NBLK, 256, DYN_SMEM>>>(out);
}

// round 7
// speedup vs baseline: 5.4982x; 1.5404x over previous
#include <cuda_runtime.h>
#include <cuda_fp16.h>
#include <stdint.h>

#define N 4096
#define D1 512
#define D2H 1024
#define KNN 10
#define MASKW (N / 64)
#define BM 128
#define NTILES (N / BM)                    // 32
#define NBLK ((NTILES * (NTILES + 1)) / 2) // 528
#define CSTR 129                           // smem C tile stride (floats)
#define STAGE_B 32768
#define DYN_SMEM (3 * STAGE_B)             // 98304: 3 stages of (A 16K + B 16K)

// ---------------- scratch (device globals; no allocation allowed) ----------
__device__ __align__(16) float g_d2[(size_t)N * N];      // 64 MB
__device__ unsigned long long g_mask[(size_t)N * MASKW]; // 2 MB
__device__ int g_asum;
__device__ float g_sq[N];
__device__ float g_rn[N];
__device__ __align__(16) __half g_ahi[(size_t)N * D1];
__device__ __align__(16) __half g_alo[(size_t)N * D1];
__device__ __align__(16) __half g_bhi[(size_t)N * D2H];

// ---------------- helpers ----------------------------------------------------
__device__ __forceinline__ uint32_t smem_u32(const void* p) {
    uint32_t a;
    asm("{ .reg .u64 t; cvta.to.shared.u64 t, %1; cvt.u32.u64 %0, t; }" : "=r"(a) : "l"(p));
    return a;
}
#define SWZ(x) ((uint32_t)(x) ^ ((((uint32_t)(x)) >> 3) & 0x70))

__device__ __forceinline__ void cp16(uint32_t s, const void* g) {
    asm volatile("cp.async.cg.shared.global [%0], [%1], 16;" :: "r"(s), "l"(g));
}
#define CP_COMMIT() asm volatile("cp.async.commit_group;" ::: "memory")
#define CP_WAIT0() asm volatile("cp.async.wait_group 0;" ::: "memory")
#define CP_WAIT1() asm volatile("cp.async.wait_group 1;" ::: "memory")

__device__ __forceinline__ void ldsm4(uint32_t& r0, uint32_t& r1, uint32_t& r2, uint32_t& r3,
                                      uint32_t addr) {
    asm volatile("ldmatrix.sync.aligned.m8n8.x4.shared.b16 {%0,%1,%2,%3}, [%4];"
                 : "=r"(r0), "=r"(r1), "=r"(r2), "=r"(r3) : "r"(addr));
}
__device__ __forceinline__ void mma16816(float c[4], const uint32_t a[4],
                                         uint32_t b0, uint32_t b1) {
    asm volatile("mma.sync.aligned.m16n8k16.row.col.f32.f16.f16.f32 "
                 "{%0,%1,%2,%3}, {%4,%5,%6,%7}, {%8,%9}, {%0,%1,%2,%3};"
                 : "+f"(c[0]), "+f"(c[1]), "+f"(c[2]), "+f"(c[3])
                 : "r"(a[0]), "r"(a[1]), "r"(a[2]), "r"(a[3]), "r"(b0), "r"(b1));
}

__device__ __forceinline__ void tri_map(int t, int& bi, int& bj) {
    int i = 0, rem = t, span = NTILES;
    while (rem >= span) { rem -= span; i++; span--; }
    bi = i;
    bj = i + rem;
}

// ---------------- setup kernels ------------------------------------------------
__global__ void k_zero() {
    int i = blockIdx.x * blockDim.x + threadIdx.x;
    const int total = N * MASKW;
    for (; i < total; i += gridDim.x * blockDim.x) g_mask[i] = 0ull;
    if (blockIdx.x == 0 && threadIdx.x == 0) g_asum = 0;
}

// fused: fp16 hi/lo split (orig), fp16 round (hidden) + row sum-of-squares
__global__ __launch_bounds__(256) void k_prep(const float* __restrict__ orig,
                                              const float* __restrict__ hid) {
    int w = blockIdx.x * 8 + (threadIdx.x >> 5);
    int lane = threadIdx.x & 31;
    if (w < N) {
        const float4* src = (const float4*)(orig + (size_t)w * D1);
        uint2* dhi = (uint2*)(g_ahi + (size_t)w * D1);
        uint2* dlo = (uint2*)(g_alo + (size_t)w * D1);
        float s = 0.f;
        #pragma unroll
        for (int ch = 0; ch < D1 / 128; ch++) {
            int c = lane + ch * 32;
            float4 v = src[c];
            s += v.x * v.x + v.y * v.y + v.z * v.z + v.w * v.w;
            __half hx = __float2half_rn(v.x), hy = __float2half_rn(v.y);
            __half hz = __float2half_rn(v.z), hw = __float2half_rn(v.w);
            __half2 h0 = {hx, hy}, h1 = {hz, hw};
            __half2 l0 = {__float2half_rn(v.x - __half2float(hx)),
                          __float2half_rn(v.y - __half2float(hy))};
            __half2 l1 = {__float2half_rn(v.z - __half2float(hz)),
                          __float2half_rn(v.w - __half2float(hw))};
            dhi[c] = make_uint2(*(uint32_t*)&h0, *(uint32_t*)&h1);
            dlo[c] = make_uint2(*(uint32_t*)&l0, *(uint32_t*)&l1);
        }
        #pragma unroll
        for (int o = 16; o; o >>= 1) s += __shfl_down_sync(0xFFFFFFFFu, s, o);
        if (lane == 0) g_sq[w] = s;
    } else {
        int r = w - N;
        const float4* src = (const float4*)(hid + (size_t)r * D2H);
        uint2* dhi = (uint2*)(g_bhi + (size_t)r * D2H);
        float s = 0.f;
        #pragma unroll
        for (int ch = 0; ch < D2H / 128; ch++) {
            int c = lane + ch * 32;
            float4 v = src[c];
            s += v.x * v.x + v.y * v.y + v.z * v.z + v.w * v.w;
            __half2 h0 = {__float2half_rn(v.x), __float2half_rn(v.y)};
            __half2 h1 = {__float2half_rn(v.z), __float2half_rn(v.w)};
            dhi[c] = make_uint2(*(uint32_t*)&h0, *(uint32_t*)&h1);
        }
        #pragma unroll
        for (int o = 16; o; o >>= 1) s += __shfl_down_sync(0xFFFFFFFFu, s, o);
        if (lane == 0) g_rn[r] = 1.0f / fmaxf(sqrtf(s), 1e-12f);
    }
}

// ---------------- HMMA mainloop: 3-stage cp.async, 1 barrier/chunk --------------
// NSEG==3: seg0 hi*hi, seg1 hi*lo, seg2 lo*hi (fp16 split; drops ~2^-24 lo*lo)
// NSEG==1: hi*hi only (plain fp16 GEMM)
template <int KSRC, int NSEG>
__device__ __forceinline__ void mma_mainloop(const __half* __restrict__ hi,
                                             const __half* __restrict__ lo,
                                             int i0, int j0, uint32_t sbase,
                                             float acc[2][8][4]) {
    const int tid = threadIdx.x;
    const int lane = tid & 31, wid = tid >> 5;
    const int wm = wid & 3, wn = wid >> 2;
    const int grp = lane >> 3, lr = lane & 7;
    const int NCH = (NSEG * KSRC) / 64;

    int rows[4], cols[4];
    #pragma unroll
    for (int t = 0; t < 4; t++) {
        int c = tid + t * 256;
        rows[t] = c >> 3;
        cols[t] = (c & 7) * 8;
    }

    auto issue = [&](int kc, int st) {
        int gk = kc * 64;
        int seg = gk / KSRC;
        int kk = gk - seg * KSRC;
        const __half* sa;
        const __half* sb;
        if (NSEG == 1) {
            sa = hi; sb = hi;
        } else {
            sa = (seg == 2) ? lo : hi;
            sb = (seg == 1) ? lo : hi;
        }
        uint32_t ab = sbase + st * STAGE_B;
        uint32_t bb = ab + 16384;
        #pragma unroll
        for (int t = 0; t < 4; t++) {
            uint32_t sw = SWZ(rows[t] * 128 + cols[t] * 2);
            cp16(ab + sw, sa + (size_t)(i0 + rows[t]) * KSRC + kk + cols[t]);
            cp16(bb + sw, sb + (size_t)(j0 + rows[t]) * KSRC + kk + cols[t]);
        }
        CP_COMMIT();
    };

    issue(0, 0);
    issue(1, 1);
    int st = 0;
    for (int kc = 0; kc < NCH; kc++) {
        if (kc + 1 < NCH) CP_WAIT1(); else CP_WAIT0();
        __syncthreads();
        if (kc + 2 < NCH) {
            int st2 = st + 2; if (st2 >= 3) st2 -= 3;
            issue(kc + 2, st2);
        }
        uint32_t ab = sbase + st * STAGE_B;
        uint32_t bb = ab + 16384;
        #pragma unroll
        for (int ks = 0; ks < 4; ks++) {
            uint32_t a[2][4], b[4][4];
            #pragma unroll
            for (int mi = 0; mi < 2; mi++) {
                int mrow = wm * 32 + mi * 16 + (grp & 1) * 8 + lr;
                uint32_t addr = ab + SWZ(mrow * 128 + ks * 32 + (grp >> 1) * 16);
                ldsm4(a[mi][0], a[mi][1], a[mi][2], a[mi][3], addr);
            }
            #pragma unroll
            for (int nb = 0; nb < 4; nb++) {
                int nrow = wn * 64 + nb * 16 + (grp & 1) * 8 + lr;
                uint32_t addr = bb + SWZ(nrow * 128 + ks * 32 + (grp >> 1) * 16);
                ldsm4(b[nb][0], b[nb][1], b[nb][2], b[nb][3], addr);
            }
            #pragma unroll
            for (int mi = 0; mi < 2; mi++)
                #pragma unroll
                for (int ni = 0; ni < 8; ni++) {
                    int nb = ni >> 1, h = ni & 1;
                    mma16816(acc[mi][ni], a[mi], b[nb][h], b[nb][h + 2]);
                }
        }
        if (++st == 3) st = 0;
    }
    __syncthreads();
}

__device__ __forceinline__ void stage_c(float* cs, float acc[2][8][4]) {
    const int lane = threadIdx.x & 31, wid = threadIdx.x >> 5;
    const int wm = wid & 3, wn = wid >> 2;
    #pragma unroll
    for (int mi = 0; mi < 2; mi++)
        #pragma unroll
        for (int ni = 0; ni < 8; ni++) {
            int r0 = wm * 32 + mi * 16 + (lane >> 2);
            int c0 = wn * 64 + ni * 8 + (lane & 3) * 2;
            cs[r0 * CSTR + c0] = acc[mi][ni][0];
            cs[r0 * CSTR + c0 + 1] = acc[mi][ni][1];
            cs[(r0 + 8) * CSTR + c0] = acc[mi][ni][2];
            cs[(r0 + 8) * CSTR + c0 + 1] = acc[mi][ni][3];
        }
}

// ---------------- GEMM 1: squared distances (fp16 3-segment split) -------------
__global__ __launch_bounds__(256, 2) void k_gemm_d2_mma() {
    extern __shared__ char dsm[];
    __shared__ float srow[128], scol[128];
    const int tid = threadIdx.x;
    int bi, bj;
    tri_map(blockIdx.x, bi, bj);
    int i0 = bi * BM, j0 = bj * BM;
    uint32_t sbase = smem_u32(dsm);

    float acc[2][8][4];
    #pragma unroll
    for (int a = 0; a < 2; a++)
        #pragma unroll
        for (int b = 0; b < 8; b++)
            #pragma unroll
            for (int c = 0; c < 4; c++) acc[a][b][c] = 0.f;

    mma_mainloop<D1, 3>(g_ahi, g_alo, i0, j0, sbase, acc);

    float* cs = (float*)dsm;
    stage_c(cs, acc);
    if (tid < 128) { srow[tid] = g_sq[i0 + tid]; scol[tid] = g_sq[j0 + tid]; }
    __syncthreads();

    #pragma unroll 4
    for (int t = 0; t < 64; t++) {
        int e = t * 256 + tid;
        int r = e >> 7, c = e & 127;
        float d2 = fmaxf(srow[r] + scol[c] - 2.0f * cs[r * CSTR + c], 0.0f);
        g_d2[(size_t)(i0 + r) * N + j0 + c] = d2;
    }
    if (bi != bj) {
        #pragma unroll 4
        for (int t = 0; t < 64; t++) {
            int e = t * 256 + tid;
            int r = e >> 7, c = e & 127;
            float d2 = fmaxf(srow[c] + scol[r] - 2.0f * cs[c * CSTR + r], 0.0f);
            g_d2[(size_t)(j0 + r) * N + i0 + c] = d2;
        }
    }
}

// ---------------- GEMM 2: cosine + masks + both planes (fp16 single) -----------
__global__ __launch_bounds__(256, 2) void k_gemm_out_mma(float* __restrict__ out) {
    extern __shared__ char dsm[];
    __shared__ float rrow[128], rcol[128];
    __shared__ unsigned long long mr[128][2];
    const int tid = threadIdx.x;
    int bi, bj;
    tri_map(blockIdx.x, bi, bj);
    int i0 = bi * BM, j0 = bj * BM;
    uint32_t sbase = smem_u32(dsm);

    float acc[2][8][4];
    #pragma unroll
    for (int a = 0; a < 2; a++)
        #pragma unroll
        for (int b = 0; b < 8; b++)
            #pragma unroll
            for (int c = 0; c < 4; c++) acc[a][b][c] = 0.f;

    mma_mainloop<D2H, 1>(g_bhi, g_bhi, i0, j0, sbase, acc);

    float* cs = (float*)dsm;
    stage_c(cs, acc);
    if (tid < 128) { rrow[tid] = g_rn[i0 + tid]; rcol[tid] = g_rn[j0 + tid]; }
    mr[tid >> 1][tid & 1] = g_mask[(size_t)(i0 + (tid >> 1)) * MASKW + (j0 >> 6) + (tid & 1)];
    __syncthreads();

    float asum = (float)g_asum;
    float Nw = 0.5f / asum;
    float Nb = 1.0f / ((float)N * (float)N - 2.0f * asum);
    const size_t NN = (size_t)N * N;

    #pragma unroll 4
    for (int t = 0; t < 64; t++) {
        int e = t * 256 + tid;
        int r = e >> 7, c = e & 127;
        float C = cs[r * CSTR + c] * rrow[r] * rcol[c];
        unsigned a = (unsigned)((mr[r][c >> 6] >> (c & 63)) & 1ull);
        size_t o = (size_t)(i0 + r) * N + j0 + c;
        out[o] = a ? 0.0f : Nb * C;
        out[NN + o] = a ? Nw * C : 0.0f;
    }
    if (bi != bj) {
        #pragma unroll 4
        for (int t = 0; t < 64; t++) {
            int e = t * 256 + tid;
            int r = e >> 7, c = e & 127;
            float C = cs[c * CSTR + r] * rrow[c] * rcol[r];
            unsigned a = (unsigned)((mr[c][r >> 6] >> (r & 63)) & 1ull);
            size_t o = (size_t)(j0 + r) * N + i0 + c;
            out[o] = a ? 0.0f : Nb * C;
            out[NN + o] = a ? Nw * C : 0.0f;
        }
    }
}

// ---------------- kNN: f32 bitonic threshold + exact candidate select ----------
__device__ __forceinline__ void cef(float& a, float& b) {
    float lo = fminf(a, b), hi = fmaxf(a, b);
    a = lo; b = hi;
}
__device__ __forceinline__ void sortf16(float k[16]) {
    #pragma unroll
    for (int kk = 2; kk <= 16; kk <<= 1) {
        #pragma unroll
        for (int j = kk >> 1; j > 0; j >>= 1) {
            #pragma unroll
            for (int i = 0; i < 16; i++) {
                int l = i ^ j;
                if (l > i) {
                    if ((i & kk) == 0) cef(k[i], k[l]);
                    else cef(k[l], k[i]);
                }
            }
        }
    }
}
__device__ __forceinline__ void mergef_xor(float k[16], int off) {
    float b[16];
    #pragma unroll
    for (int i = 0; i < 16; i++) b[i] = __shfl_xor_sync(0xFFFFFFFFu, k[15 - i], off);
    #pragma unroll
    for (int i = 0; i < 16; i++) k[i] = fminf(k[i], b[i]);
    #pragma unroll
    for (int s = 8; s > 0; s >>= 1) {
        #pragma unroll
        for (int i = 0; i < 16; i++)
            if (!(i & s)) cef(k[i], k[i | s]);
    }
}

__global__ __launch_bounds__(256) void k_knn() {
    int row = blockIdx.x, tid = threadIdx.x;
    int lane = tid & 31, wid = tid >> 5;
    const float4* dr = (const float4*)(g_d2 + (size_t)row * N);

    float4 q[4];
    #pragma unroll
    for (int r = 0; r < 4; r++) q[r] = dr[tid + r * 256];

    float s[16];
    #pragma unroll
    for (int r = 0; r < 4; r++) {
        s[r * 4 + 0] = q[r].x; s[r * 4 + 1] = q[r].y;
        s[r * 4 + 2] = q[r].z; s[r * 4 + 3] = q[r].w;
    }
    sortf16(s);
    mergef_xor(s, 1); mergef_xor(s, 2); mergef_xor(s, 4);
    mergef_xor(s, 8); mergef_xor(s, 16);

    __shared__ float lists[8][16];
    __shared__ float shT;
    __shared__ int cnt;
    __shared__ unsigned long long cand[64];
    if (lane == 0) {
        #pragma unroll
        for (int t = 0; t < 16; t++) lists[wid][t] = s[t];
    }
    if (tid == 0) cnt = 0;
    __syncthreads();

    if (tid < 32) {
        float m[16];
        if (lane < 8) {
            #pragma unroll
            for (int t = 0; t < 16; t++) m[t] = lists[lane][t];
        } else {
            #pragma unroll
            for (int t = 0; t < 16; t++) m[t] = 3.4e38f;
        }
        mergef_xor(m, 1); mergef_xor(m, 2); mergef_xor(m, 4);
        if (lane == 0) shT = m[KNN - 1]; // 10th smallest value
    }
    __syncthreads();

    float T = shT;
    #pragma unroll
    for (int r = 0; r < 4; r++) {
        const float* qe = (const float*)&q[r];
        #pragma unroll
        for (int e = 0; e < 4; e++) {
            float val = qe[e];
            if (val <= T) {
                int p = atomicAdd(&cnt, 1);
                if (p < 64) {
                    unsigned col = (unsigned)((tid + r * 256) * 4 + e);
                    cand[p] = ((unsigned long long)__float_as_uint(val) << 32) | col;
                }
            }
        }
    }
    __syncthreads();

    if (tid == 0) {
        int m = cnt < 64 ? cnt : 64;
        for (int t = 0; t < KNN; t++) {
            int best = t;
            for (int u = t + 1; u < m; u++)
                if (cand[u] < cand[best]) best = u;
            unsigned long long tmp = cand[best];
            cand[best] = cand[t]; cand[t] = tmp;
            unsigned j = (unsigned)tmp;
            atomicOr(&g_mask[(size_t)row * MASKW + (j >> 6)], 1ull << (j & 63));
            atomicOr(&g_mask[(size_t)j * MASKW + (row >> 6)], 1ull << (row & 63));
        }
    }
}

__global__ void k_count() {
    int i = blockIdx.x * blockDim.x + threadIdx.x;
    int cnt = 0;
    const int total = N * MASKW;
    for (; i < total; i += gridDim.x * blockDim.x) cnt += __popcll(g_mask[i]);
    #pragma unroll
    for (int o = 16; o; o >>= 1) cnt += __shfl_down_sync(0xFFFFFFFFu, cnt, o);
    if ((threadIdx.x & 31) == 0 && cnt) atomicAdd(&g_asum, cnt);
}

// ---------------------------------------------------------------------------
extern "C" void kernel_launch(void* const* d_in, const int* in_sizes, int n_in,
                              void* d_out, int out_size) {
    const float* orig = (const float*)d_in[0]; // [4096, 512]
    const float* hid  = (const float*)d_in[1]; // [4096, 1024]
    float* out = (float*)d_out;                // [2, 4096, 4096]

    cudaFuncSetAttribute(k_gemm_d2_mma, cudaFuncAttributeMaxDynamicSharedMemorySize, DYN_SMEM);
    cudaFuncSetAttribute(k_gemm_out_mma, cudaFuncAttributeMaxDynamicSharedMemorySize, DYN_SMEM);

    k_zero<<<256, 256>>>();
    k_prep<<<1024, 256>>>(orig, hid);
    k_gemm_d2_mma<<<NBLK, 256, DYN_SMEM>>>();
    k_knn<<<N, 256>>>();
    k_count<<<256, 256>>>();
    k_gemm_out_mma<<<NBLK, 256, DYN_SMEM>>>(out);
}

// round 8
// speedup vs baseline: 5.8246x; 1.0594x over previous
#include <cuda_runtime.h>
#include <cuda_fp16.h>
#include <stdint.h>

#define N 4096
#define D1 512
#define D2H 1024
#define KNN 10
#define MASKW (N / 64)
#define BM 128
#define NTILES (N / BM)                    // 32
#define NBLK ((NTILES * (NTILES + 1)) / 2) // 528
#define CSTR 129                           // smem C tile stride (floats)
#define STAGE_B 32768
#define DYN_SMEM (3 * STAGE_B)             // 98304: 3 stages of (A 16K + B 16K)

// ---------------- scratch (device globals; no allocation allowed) ----------
__device__ __align__(16) float g_d2[(size_t)N * N];      // 64 MB
__device__ unsigned long long g_mask[(size_t)N * MASKW]; // 2 MB
__device__ int g_asum;
__device__ float g_sq[N];
__device__ float g_rn[N];
__device__ __align__(16) __half g_ahi[(size_t)N * D1];
__device__ __align__(16) __half g_alo[(size_t)N * D1];
__device__ __align__(16) __half g_bhi[(size_t)N * D2H];

// ---------------- helpers ----------------------------------------------------
__device__ __forceinline__ uint32_t smem_u32(const void* p) {
    uint32_t a;
    asm("{ .reg .u64 t; cvta.to.shared.u64 t, %1; cvt.u32.u64 %0, t; }" : "=r"(a) : "l"(p));
    return a;
}
#define SWZ(x) ((uint32_t)(x) ^ ((((uint32_t)(x)) >> 3) & 0x70))

__device__ __forceinline__ void cp16(uint32_t s, const void* g) {
    asm volatile("cp.async.cg.shared.global [%0], [%1], 16;" :: "r"(s), "l"(g));
}
#define CP_COMMIT() asm volatile("cp.async.commit_group;" ::: "memory")
#define CP_WAIT0() asm volatile("cp.async.wait_group 0;" ::: "memory")
#define CP_WAIT1() asm volatile("cp.async.wait_group 1;" ::: "memory")

__device__ __forceinline__ void ldsm4(uint32_t& r0, uint32_t& r1, uint32_t& r2, uint32_t& r3,
                                      uint32_t addr) {
    asm volatile("ldmatrix.sync.aligned.m8n8.x4.shared.b16 {%0,%1,%2,%3}, [%4];"
                 : "=r"(r0), "=r"(r1), "=r"(r2), "=r"(r3) : "r"(addr));
}
__device__ __forceinline__ void mma16816(float c[4], const uint32_t a[4],
                                         uint32_t b0, uint32_t b1) {
    asm volatile("mma.sync.aligned.m16n8k16.row.col.f32.f16.f16.f32 "
                 "{%0,%1,%2,%3}, {%4,%5,%6,%7}, {%8,%9}, {%0,%1,%2,%3};"
                 : "+f"(c[0]), "+f"(c[1]), "+f"(c[2]), "+f"(c[3])
                 : "r"(a[0]), "r"(a[1]), "r"(a[2]), "r"(a[3]), "r"(b0), "r"(b1));
}

__device__ __forceinline__ void tri_map(int t, int& bi, int& bj) {
    int i = 0, rem = t, span = NTILES;
    while (rem >= span) { rem -= span; i++; span--; }
    bi = i;
    bj = i + rem;
}

// ---------------- prep: split + rowstats + mask zero (fused) -------------------
__global__ __launch_bounds__(256) void k_prep(const float* __restrict__ orig,
                                              const float* __restrict__ hid) {
    // zero one slice of the mask (1024 blocks * 256 threads == N*MASKW words)
    g_mask[blockIdx.x * 256 + threadIdx.x] = 0ull;
    if (blockIdx.x == 0 && threadIdx.x == 0) g_asum = 0;

    int w = blockIdx.x * 8 + (threadIdx.x >> 5);
    int lane = threadIdx.x & 31;
    if (w < N) {
        const float4* src = (const float4*)(orig + (size_t)w * D1);
        uint2* dhi = (uint2*)(g_ahi + (size_t)w * D1);
        uint2* dlo = (uint2*)(g_alo + (size_t)w * D1);
        float s = 0.f;
        #pragma unroll
        for (int ch = 0; ch < D1 / 128; ch++) {
            int c = lane + ch * 32;
            float4 v = src[c];
            s += v.x * v.x + v.y * v.y + v.z * v.z + v.w * v.w;
            __half hx = __float2half_rn(v.x), hy = __float2half_rn(v.y);
            __half hz = __float2half_rn(v.z), hw = __float2half_rn(v.w);
            __half2 h0 = {hx, hy}, h1 = {hz, hw};
            __half2 l0 = {__float2half_rn(v.x - __half2float(hx)),
                          __float2half_rn(v.y - __half2float(hy))};
            __half2 l1 = {__float2half_rn(v.z - __half2float(hz)),
                          __float2half_rn(v.w - __half2float(hw))};
            dhi[c] = make_uint2(*(uint32_t*)&h0, *(uint32_t*)&h1);
            dlo[c] = make_uint2(*(uint32_t*)&l0, *(uint32_t*)&l1);
        }
        #pragma unroll
        for (int o = 16; o; o >>= 1) s += __shfl_down_sync(0xFFFFFFFFu, s, o);
        if (lane == 0) g_sq[w] = s;
    } else {
        int r = w - N;
        const float4* src = (const float4*)(hid + (size_t)r * D2H);
        uint2* dhi = (uint2*)(g_bhi + (size_t)r * D2H);
        float s = 0.f;
        #pragma unroll
        for (int ch = 0; ch < D2H / 128; ch++) {
            int c = lane + ch * 32;
            float4 v = src[c];
            s += v.x * v.x + v.y * v.y + v.z * v.z + v.w * v.w;
            __half2 h0 = {__float2half_rn(v.x), __float2half_rn(v.y)};
            __half2 h1 = {__float2half_rn(v.z), __float2half_rn(v.w)};
            dhi[c] = make_uint2(*(uint32_t*)&h0, *(uint32_t*)&h1);
        }
        #pragma unroll
        for (int o = 16; o; o >>= 1) s += __shfl_down_sync(0xFFFFFFFFu, s, o);
        if (lane == 0) g_rn[r] = 1.0f / fmaxf(sqrtf(s), 1e-12f);
    }
}

// ---------------- HMMA mainloop: 3-stage cp.async, 1 barrier/chunk --------------
// NSEG==3: seg0 hi*hi, seg1 hi*lo, seg2 lo*hi (fp16 split; drops ~2^-24 lo*lo)
// NSEG==1: hi*hi only (plain fp16 GEMM)
template <int KSRC, int NSEG>
__device__ __forceinline__ void mma_mainloop(const __half* __restrict__ hi,
                                             const __half* __restrict__ lo,
                                             int i0, int j0, uint32_t sbase,
                                             float acc[2][8][4]) {
    const int tid = threadIdx.x;
    const int lane = tid & 31, wid = tid >> 5;
    const int wm = wid & 3, wn = wid >> 2;
    const int grp = lane >> 3, lr = lane & 7;
    const int NCH = (NSEG * KSRC) / 64;

    int rows[4], cols[4];
    #pragma unroll
    for (int t = 0; t < 4; t++) {
        int c = tid + t * 256;
        rows[t] = c >> 3;
        cols[t] = (c & 7) * 8;
    }

    auto issue = [&](int kc, int st) {
        int gk = kc * 64;
        int seg = gk / KSRC;
        int kk = gk - seg * KSRC;
        const __half* sa;
        const __half* sb;
        if (NSEG == 1) {
            sa = hi; sb = hi;
        } else {
            sa = (seg == 2) ? lo : hi;
            sb = (seg == 1) ? lo : hi;
        }
        uint32_t ab = sbase + st * STAGE_B;
        uint32_t bb = ab + 16384;
        #pragma unroll
        for (int t = 0; t < 4; t++) {
            uint32_t sw = SWZ(rows[t] * 128 + cols[t] * 2);
            cp16(ab + sw, sa + (size_t)(i0 + rows[t]) * KSRC + kk + cols[t]);
            cp16(bb + sw, sb + (size_t)(j0 + rows[t]) * KSRC + kk + cols[t]);
        }
        CP_COMMIT();
    };

    issue(0, 0);
    issue(1, 1);
    int st = 0;
    for (int kc = 0; kc < NCH; kc++) {
        if (kc + 1 < NCH) CP_WAIT1(); else CP_WAIT0();
        __syncthreads();
        if (kc + 2 < NCH) {
            int st2 = st + 2; if (st2 >= 3) st2 -= 3;
            issue(kc + 2, st2);
        }
        uint32_t ab = sbase + st * STAGE_B;
        uint32_t bb = ab + 16384;
        #pragma unroll
        for (int ks = 0; ks < 4; ks++) {
            uint32_t a[2][4], b[4][4];
            #pragma unroll
            for (int mi = 0; mi < 2; mi++) {
                int mrow = wm * 32 + mi * 16 + (grp & 1) * 8 + lr;
                uint32_t addr = ab + SWZ(mrow * 128 + ks * 32 + (grp >> 1) * 16);
                ldsm4(a[mi][0], a[mi][1], a[mi][2], a[mi][3], addr);
            }
            #pragma unroll
            for (int nb = 0; nb < 4; nb++) {
                int nrow = wn * 64 + nb * 16 + (grp & 1) * 8 + lr;
                uint32_t addr = bb + SWZ(nrow * 128 + ks * 32 + (grp >> 1) * 16);
                ldsm4(b[nb][0], b[nb][1], b[nb][2], b[nb][3], addr);
            }
            #pragma unroll
            for (int mi = 0; mi < 2; mi++)
                #pragma unroll
                for (int ni = 0; ni < 8; ni++) {
                    int nb = ni >> 1, h = ni & 1;
                    mma16816(acc[mi][ni], a[mi], b[nb][h], b[nb][h + 2]);
                }
        }
        if (++st == 3) st = 0;
    }
    __syncthreads();
}

__device__ __forceinline__ void stage_c(float* cs, float acc[2][8][4]) {
    const int lane = threadIdx.x & 31, wid = threadIdx.x >> 5;
    const int wm = wid & 3, wn = wid >> 2;
    #pragma unroll
    for (int mi = 0; mi < 2; mi++)
        #pragma unroll
        for (int ni = 0; ni < 8; ni++) {
            int r0 = wm * 32 + mi * 16 + (lane >> 2);
            int c0 = wn * 64 + ni * 8 + (lane & 3) * 2;
            cs[r0 * CSTR + c0] = acc[mi][ni][0];
            cs[r0 * CSTR + c0 + 1] = acc[mi][ni][1];
            cs[(r0 + 8) * CSTR + c0] = acc[mi][ni][2];
            cs[(r0 + 8) * CSTR + c0 + 1] = acc[mi][ni][3];
        }
}

// ---------------- GEMM 1: squared distances (fp16 3-segment split) -------------
__global__ __launch_bounds__(256, 2) void k_gemm_d2_mma() {
    extern __shared__ char dsm[];
    __shared__ float srow[128], scol[128];
    const int tid = threadIdx.x;
    int bi, bj;
    tri_map(blockIdx.x, bi, bj);
    int i0 = bi * BM, j0 = bj * BM;
    uint32_t sbase = smem_u32(dsm);

    float acc[2][8][4];
    #pragma unroll
    for (int a = 0; a < 2; a++)
        #pragma unroll
        for (int b = 0; b < 8; b++)
            #pragma unroll
            for (int c = 0; c < 4; c++) acc[a][b][c] = 0.f;

    mma_mainloop<D1, 3>(g_ahi, g_alo, i0, j0, sbase, acc);

    float* cs = (float*)dsm;
    stage_c(cs, acc);
    if (tid < 128) { srow[tid] = g_sq[i0 + tid]; scol[tid] = g_sq[j0 + tid]; }
    __syncthreads();

    #pragma unroll 4
    for (int t = 0; t < 64; t++) {
        int e = t * 256 + tid;
        int r = e >> 7, c = e & 127;
        float d2 = fmaxf(srow[r] + scol[c] - 2.0f * cs[r * CSTR + c], 0.0f);
        g_d2[(size_t)(i0 + r) * N + j0 + c] = d2;
    }
    if (bi != bj) {
        #pragma unroll 4
        for (int t = 0; t < 64; t++) {
            int e = t * 256 + tid;
            int r = e >> 7, c = e & 127;
            float d2 = fmaxf(srow[c] + scol[r] - 2.0f * cs[c * CSTR + r], 0.0f);
            g_d2[(size_t)(j0 + r) * N + i0 + c] = d2;
        }
    }
}

// ---------------- GEMM 2: cosine + masks + both planes (fp16 single) -----------
__global__ __launch_bounds__(256, 2) void k_gemm_out_mma(float* __restrict__ out) {
    extern __shared__ char dsm[];
    __shared__ float rrow[128], rcol[128];
    __shared__ unsigned long long mr[128][2];
    const int tid = threadIdx.x;
    int bi, bj;
    tri_map(blockIdx.x, bi, bj);
    int i0 = bi * BM, j0 = bj * BM;
    uint32_t sbase = smem_u32(dsm);

    float acc[2][8][4];
    #pragma unroll
    for (int a = 0; a < 2; a++)
        #pragma unroll
        for (int b = 0; b < 8; b++)
            #pragma unroll
            for (int c = 0; c < 4; c++) acc[a][b][c] = 0.f;

    mma_mainloop<D2H, 1>(g_bhi, g_bhi, i0, j0, sbase, acc);

    float* cs = (float*)dsm;
    stage_c(cs, acc);
    if (tid < 128) { rrow[tid] = g_rn[i0 + tid]; rcol[tid] = g_rn[j0 + tid]; }
    mr[tid >> 1][tid & 1] = g_mask[(size_t)(i0 + (tid >> 1)) * MASKW + (j0 >> 6) + (tid & 1)];
    __syncthreads();

    float asum = (float)g_asum;
    float Nw = 0.5f / asum;
    float Nb = 1.0f / ((float)N * (float)N - 2.0f * asum);
    const size_t NN = (size_t)N * N;

    #pragma unroll 4
    for (int t = 0; t < 64; t++) {
        int e = t * 256 + tid;
        int r = e >> 7, c = e & 127;
        float C = cs[r * CSTR + c] * rrow[r] * rcol[c];
        unsigned a = (unsigned)((mr[r][c >> 6] >> (c & 63)) & 1ull);
        size_t o = (size_t)(i0 + r) * N + j0 + c;
        out[o] = a ? 0.0f : Nb * C;
        out[NN + o] = a ? Nw * C : 0.0f;
    }
    if (bi != bj) {
        #pragma unroll 4
        for (int t = 0; t < 64; t++) {
            int e = t * 256 + tid;
            int r = e >> 7, c = e & 127;
            float C = cs[c * CSTR + r] * rrow[c] * rcol[r];
            unsigned a = (unsigned)((mr[c][r >> 6] >> (r & 63)) & 1ull);
            size_t o = (size_t)(j0 + r) * N + i0 + c;
            out[o] = a ? 0.0f : Nb * C;
            out[NN + o] = a ? Nw * C : 0.0f;
        }
    }
}

// ---------------- kNN: thread-min threshold + exact candidate select ----------
__device__ __forceinline__ void cef(float& a, float& b) {
    float lo = fminf(a, b), hi = fmaxf(a, b);
    a = lo; b = hi;
}
__device__ __forceinline__ void sortf16(float k[16]) {
    #pragma unroll
    for (int kk = 2; kk <= 16; kk <<= 1) {
        #pragma unroll
        for (int j = kk >> 1; j > 0; j >>= 1) {
            #pragma unroll
            for (int i = 0; i < 16; i++) {
                int l = i ^ j;
                if (l > i) {
                    if ((i & kk) == 0) cef(k[i], k[l]);
                    else cef(k[l], k[i]);
                }
            }
        }
    }
}
__device__ __forceinline__ void mergef_xor(float k[16], int off) {
    float b[16];
    #pragma unroll
    for (int i = 0; i < 16; i++) b[i] = __shfl_xor_sync(0xFFFFFFFFu, k[15 - i], off);
    #pragma unroll
    for (int i = 0; i < 16; i++) k[i] = fminf(k[i], b[i]);
    #pragma unroll
    for (int s = 8; s > 0; s >>= 1) {
        #pragma unroll
        for (int i = 0; i < 16; i++)
            if (!(i & s)) cef(k[i], k[i | s]);
    }
}

__global__ __launch_bounds__(256) void k_knn() {
    int row = blockIdx.x, tid = threadIdx.x;
    int lane = tid & 31;
    const float4* dr = (const float4*)(g_d2 + (size_t)row * N);

    float4 q[4];
    #pragma unroll
    for (int r = 0; r < 4; r++) q[r] = dr[tid + r * 256];

    // phase 1: per-thread min of 16 values
    float tmin = 3.4e38f;
    #pragma unroll
    for (int r = 0; r < 4; r++) {
        tmin = fminf(tmin, fminf(fminf(q[r].x, q[r].y), fminf(q[r].z, q[r].w)));
    }

    __shared__ float mins[256];
    __shared__ float shT;
    __shared__ int cnt;
    __shared__ unsigned long long cand[512];
    mins[tid] = tmin;
    if (tid == 0) cnt = 0;
    __syncthreads();

    // phase 2: warp 0 finds T = 10th smallest of 256 minima (upper bound on
    // the true 10th smallest, since each group-min <= every value it covers)
    if (tid < 32) {
        float m[16];
        #pragma unroll
        for (int t = 0; t < 8; t++) m[t] = mins[lane * 8 + t];
        #pragma unroll
        for (int t = 8; t < 16; t++) m[t] = 3.4e38f;
        sortf16(m);
        mergef_xor(m, 1); mergef_xor(m, 2); mergef_xor(m, 4);
        mergef_xor(m, 8); mergef_xor(m, 16);
        if (lane == 0) shT = m[KNN - 1];
    }
    __syncthreads();

    // phase 3: collect all values <= T (superset of true top-10; >=10 entries)
    float T = shT;
    #pragma unroll
    for (int r = 0; r < 4; r++) {
        const float* qe = (const float*)&q[r];
        #pragma unroll
        for (int e = 0; e < 4; e++) {
            float val = qe[e];
            if (val <= T) {
                int p = atomicAdd(&cnt, 1);
                if (p < 512) {
                    unsigned col = (unsigned)((tid + r * 256) * 4 + e);
                    cand[p] = ((unsigned long long)__float_as_uint(val) << 32) | col;
                }
            }
        }
    }
    __syncthreads();

    // phase 4: exact selection of 10 smallest (value, col) keys
    if (tid == 0) {
        int m = cnt < 512 ? cnt : 512;
        for (int t = 0; t < KNN; t++) {
            int best = t;
            for (int u = t + 1; u < m; u++)
                if (cand[u] < cand[best]) best = u;
            unsigned long long tmp = cand[best];
            cand[best] = cand[t]; cand[t] = tmp;
            unsigned j = (unsigned)tmp;
            atomicOr(&g_mask[(size_t)row * MASKW + (j >> 6)], 1ull << (j & 63));
            atomicOr(&g_mask[(size_t)j * MASKW + (row >> 6)], 1ull << (row & 63));
        }
    }
}

__global__ void k_count() {
    int i = blockIdx.x * blockDim.x + threadIdx.x;
    int cnt = 0;
    const int total = N * MASKW;
    for (; i < total; i += gridDim.x * blockDim.x) cnt += __popcll(g_mask[i]);
    #pragma unroll
    for (int o = 16; o; o >>= 1) cnt += __shfl_down_sync(0xFFFFFFFFu, cnt, o);
    if ((threadIdx.x & 31) == 0 && cnt) atomicAdd(&g_asum, cnt);
}

// ---------------------------------------------------------------------------
extern "C" void kernel_launch(void* const* d_in, const int* in_sizes, int n_in,
                              void* d_out, int out_size) {
    const float* orig = (const float*)d_in[0]; // [4096, 512]
    const float* hid  = (const float*)d_in[1]; // [4096, 1024]
    float* out = (float*)d_out;                // [2, 4096, 4096]

    cudaFuncSetAttribute(k_gemm_d2_mma, cudaFuncAttributeMaxDynamicSharedMemorySize, DYN_SMEM);
    cudaFuncSetAttribute(k_gemm_out_mma, cudaFuncAttributeMaxDynamicSharedMemorySize, DYN_SMEM);

    k_prep<<<1024, 256>>>(orig, hid);
    k_gemm_d2_mma<<<NBLK, 256, DYN_SMEM>>>();
    k_knn<<<N, 256>>>();
    k_count<<<256, 256>>>();
    k_gemm_out_mma<<<NBLK, 256, DYN_SMEM>>>(out);
}

// round 9
// speedup vs baseline: 6.0106x; 1.0319x over previous
#include <cuda_runtime.h>
#include <cuda_fp16.h>
#include <stdint.h>

#define N 4096
#define D1 512
#define D2H 1024
#define KNN 10
#define MASKW (N / 64)
#define BM 128
#define NTILES (N / BM)                    // 32
#define NBLK ((NTILES * (NTILES + 1)) / 2) // 528
#define CSTR 129                           // smem C tile stride (floats)
#define STAGE_B 32768
#define DYN_SMEM (3 * STAGE_B)             // 98304: 3 stages of (A 16K + B 16K)

// ---------------- scratch (device globals; no allocation allowed) ----------
__device__ __align__(16) float g_d2[(size_t)N * N];      // 64 MB
__device__ __align__(16) float g_tmin[(size_t)N * NTILES]; // per-(row,tile) min
__device__ unsigned long long g_mask[(size_t)N * MASKW]; // 2 MB
__device__ int g_asum;
__device__ float g_sq[N];
__device__ float g_rn[N];
__device__ __align__(16) __half g_ahi[(size_t)N * D1];
__device__ __align__(16) __half g_alo[(size_t)N * D1];
__device__ __align__(16) __half g_bhi[(size_t)N * D2H];

// ---------------- helpers ----------------------------------------------------
__device__ __forceinline__ uint32_t smem_u32(const void* p) {
    uint32_t a;
    asm("{ .reg .u64 t; cvta.to.shared.u64 t, %1; cvt.u32.u64 %0, t; }" : "=r"(a) : "l"(p));
    return a;
}
#define SWZ(x) ((uint32_t)(x) ^ ((((uint32_t)(x)) >> 3) & 0x70))

__device__ __forceinline__ void cp16(uint32_t s, const void* g) {
    asm volatile("cp.async.cg.shared.global [%0], [%1], 16;" :: "r"(s), "l"(g));
}
#define CP_COMMIT() asm volatile("cp.async.commit_group;" ::: "memory")
#define CP_WAIT0() asm volatile("cp.async.wait_group 0;" ::: "memory")
#define CP_WAIT1() asm volatile("cp.async.wait_group 1;" ::: "memory")

__device__ __forceinline__ void ldsm4(uint32_t& r0, uint32_t& r1, uint32_t& r2, uint32_t& r3,
                                      uint32_t addr) {
    asm volatile("ldmatrix.sync.aligned.m8n8.x4.shared.b16 {%0,%1,%2,%3}, [%4];"
                 : "=r"(r0), "=r"(r1), "=r"(r2), "=r"(r3) : "r"(addr));
}
__device__ __forceinline__ void mma16816(float c[4], const uint32_t a[4],
                                         uint32_t b0, uint32_t b1) {
    asm volatile("mma.sync.aligned.m16n8k16.row.col.f32.f16.f16.f32 "
                 "{%0,%1,%2,%3}, {%4,%5,%6,%7}, {%8,%9}, {%0,%1,%2,%3};"
                 : "+f"(c[0]), "+f"(c[1]), "+f"(c[2]), "+f"(c[3])
                 : "r"(a[0]), "r"(a[1]), "r"(a[2]), "r"(a[3]), "r"(b0), "r"(b1));
}

__device__ __forceinline__ void tri_map(int t, int& bi, int& bj) {
    int i = 0, rem = t, span = NTILES;
    while (rem >= span) { rem -= span; i++; span--; }
    bi = i;
    bj = i + rem;
}

// ---------------- prep: split + rowstats + mask zero (fused) -------------------
__global__ __launch_bounds__(256) void k_prep(const float* __restrict__ orig,
                                              const float* __restrict__ hid) {
    g_mask[blockIdx.x * 256 + threadIdx.x] = 0ull;
    if (blockIdx.x == 0 && threadIdx.x == 0) g_asum = 0;

    int w = blockIdx.x * 8 + (threadIdx.x >> 5);
    int lane = threadIdx.x & 31;
    if (w < N) {
        const float4* src = (const float4*)(orig + (size_t)w * D1);
        uint2* dhi = (uint2*)(g_ahi + (size_t)w * D1);
        uint2* dlo = (uint2*)(g_alo + (size_t)w * D1);
        float s = 0.f;
        #pragma unroll
        for (int ch = 0; ch < D1 / 128; ch++) {
            int c = lane + ch * 32;
            float4 v = src[c];
            s += v.x * v.x + v.y * v.y + v.z * v.z + v.w * v.w;
            __half hx = __float2half_rn(v.x), hy = __float2half_rn(v.y);
            __half hz = __float2half_rn(v.z), hw = __float2half_rn(v.w);
            __half2 h0 = {hx, hy}, h1 = {hz, hw};
            __half2 l0 = {__float2half_rn(v.x - __half2float(hx)),
                          __float2half_rn(v.y - __half2float(hy))};
            __half2 l1 = {__float2half_rn(v.z - __half2float(hz)),
                          __float2half_rn(v.w - __half2float(hw))};
            dhi[c] = make_uint2(*(uint32_t*)&h0, *(uint32_t*)&h1);
            dlo[c] = make_uint2(*(uint32_t*)&l0, *(uint32_t*)&l1);
        }
        #pragma unroll
        for (int o = 16; o; o >>= 1) s += __shfl_down_sync(0xFFFFFFFFu, s, o);
        if (lane == 0) g_sq[w] = s;
    } else {
        int r = w - N;
        const float4* src = (const float4*)(hid + (size_t)r * D2H);
        uint2* dhi = (uint2*)(g_bhi + (size_t)r * D2H);
        float s = 0.f;
        #pragma unroll
        for (int ch = 0; ch < D2H / 128; ch++) {
            int c = lane + ch * 32;
            float4 v = src[c];
            s += v.x * v.x + v.y * v.y + v.z * v.z + v.w * v.w;
            __half2 h0 = {__float2half_rn(v.x), __float2half_rn(v.y)};
            __half2 h1 = {__float2half_rn(v.z), __float2half_rn(v.w)};
            dhi[c] = make_uint2(*(uint32_t*)&h0, *(uint32_t*)&h1);
        }
        #pragma unroll
        for (int o = 16; o; o >>= 1) s += __shfl_down_sync(0xFFFFFFFFu, s, o);
        if (lane == 0) g_rn[r] = 1.0f / fmaxf(sqrtf(s), 1e-12f);
    }
}

// ---------------- HMMA mainloop: 3-stage cp.async, 1 barrier/chunk --------------
template <int KSRC, int NSEG>
__device__ __forceinline__ void mma_mainloop(const __half* __restrict__ hi,
                                             const __half* __restrict__ lo,
                                             int i0, int j0, uint32_t sbase,
                                             float acc[2][8][4]) {
    const int tid = threadIdx.x;
    const int lane = tid & 31, wid = tid >> 5;
    const int wm = wid & 3, wn = wid >> 2;
    const int grp = lane >> 3, lr = lane & 7;
    const int NCH = (NSEG * KSRC) / 64;

    int rows[4], cols[4];
    #pragma unroll
    for (int t = 0; t < 4; t++) {
        int c = tid + t * 256;
        rows[t] = c >> 3;
        cols[t] = (c & 7) * 8;
    }

    auto issue = [&](int kc, int st) {
        int gk = kc * 64;
        int seg = gk / KSRC;
        int kk = gk - seg * KSRC;
        const __half* sa;
        const __half* sb;
        if (NSEG == 1) {
            sa = hi; sb = hi;
        } else {
            sa = (seg == 2) ? lo : hi;
            sb = (seg == 1) ? lo : hi;
        }
        uint32_t ab = sbase + st * STAGE_B;
        uint32_t bb = ab + 16384;
        #pragma unroll
        for (int t = 0; t < 4; t++) {
            uint32_t sw = SWZ(rows[t] * 128 + cols[t] * 2);
            cp16(ab + sw, sa + (size_t)(i0 + rows[t]) * KSRC + kk + cols[t]);
            cp16(bb + sw, sb + (size_t)(j0 + rows[t]) * KSRC + kk + cols[t]);
        }
        CP_COMMIT();
    };

    issue(0, 0);
    issue(1, 1);
    int st = 0;
    for (int kc = 0; kc < NCH; kc++) {
        if (kc + 1 < NCH) CP_WAIT1(); else CP_WAIT0();
        __syncthreads();
        if (kc + 2 < NCH) {
            int st2 = st + 2; if (st2 >= 3) st2 -= 3;
            issue(kc + 2, st2);
        }
        uint32_t ab = sbase + st * STAGE_B;
        uint32_t bb = ab + 16384;
        #pragma unroll
        for (int ks = 0; ks < 4; ks++) {
            uint32_t a[2][4], b[4][4];
            #pragma unroll
            for (int mi = 0; mi < 2; mi++) {
                int mrow = wm * 32 + mi * 16 + (grp & 1) * 8 + lr;
                uint32_t addr = ab + SWZ(mrow * 128 + ks * 32 + (grp >> 1) * 16);
                ldsm4(a[mi][0], a[mi][1], a[mi][2], a[mi][3], addr);
            }
            #pragma unroll
            for (int nb = 0; nb < 4; nb++) {
                int nrow = wn * 64 + nb * 16 + (grp & 1) * 8 + lr;
                uint32_t addr = bb + SWZ(nrow * 128 + ks * 32 + (grp >> 1) * 16);
                ldsm4(b[nb][0], b[nb][1], b[nb][2], b[nb][3], addr);
            }
            #pragma unroll
            for (int mi = 0; mi < 2; mi++)
                #pragma unroll
                for (int ni = 0; ni < 8; ni++) {
                    int nb = ni >> 1, h = ni & 1;
                    mma16816(acc[mi][ni], a[mi], b[nb][h], b[nb][h + 2]);
                }
        }
        if (++st == 3) st = 0;
    }
    __syncthreads();
}

__device__ __forceinline__ void stage_c(float* cs, float acc[2][8][4]) {
    const int lane = threadIdx.x & 31, wid = threadIdx.x >> 5;
    const int wm = wid & 3, wn = wid >> 2;
    #pragma unroll
    for (int mi = 0; mi < 2; mi++)
        #pragma unroll
        for (int ni = 0; ni < 8; ni++) {
            int r0 = wm * 32 + mi * 16 + (lane >> 2);
            int c0 = wn * 64 + ni * 8 + (lane & 3) * 2;
            cs[r0 * CSTR + c0] = acc[mi][ni][0];
            cs[r0 * CSTR + c0 + 1] = acc[mi][ni][1];
            cs[(r0 + 8) * CSTR + c0] = acc[mi][ni][2];
            cs[(r0 + 8) * CSTR + c0 + 1] = acc[mi][ni][3];
        }
}

// ---------------- GEMM 1: d2 (fp16 3-seg) + per-(row,tile) minima --------------
__global__ __launch_bounds__(256, 2) void k_gemm_d2_mma() {
    extern __shared__ char dsm[];
    __shared__ float srow[128], scol[128];
    __shared__ float cmin[128];
    const int tid = threadIdx.x;
    int bi, bj;
    tri_map(blockIdx.x, bi, bj);
    int i0 = bi * BM, j0 = bj * BM;
    uint32_t sbase = smem_u32(dsm);

    float acc[2][8][4];
    #pragma unroll
    for (int a = 0; a < 2; a++)
        #pragma unroll
        for (int b = 0; b < 8; b++)
            #pragma unroll
            for (int c = 0; c < 4; c++) acc[a][b][c] = 0.f;

    mma_mainloop<D1, 3>(g_ahi, g_alo, i0, j0, sbase, acc);

    float* cs = (float*)dsm;
    stage_c(cs, acc);
    if (tid < 128) { srow[tid] = g_sq[i0 + tid]; scol[tid] = g_sq[j0 + tid]; }
    __syncthreads();

    // direct tile: thread has fixed j-col (tid&127), scans 64 i-rows
    float m1 = 3.4e38f;
    #pragma unroll 4
    for (int t = 0; t < 64; t++) {
        int e = t * 256 + tid;
        int r = e >> 7, c = e & 127;
        float d2 = fmaxf(srow[r] + scol[c] - 2.0f * cs[r * CSTR + c], 0.0f);
        m1 = fminf(m1, d2);
        g_d2[(size_t)(i0 + r) * N + j0 + c] = d2;
    }
    // combine 2 threads per column -> min over all 128 i-rows for row (j0+c)
    if (tid < 128) cmin[tid] = m1;
    __syncthreads();
    if (tid >= 128) cmin[tid - 128] = fminf(cmin[tid - 128], m1);
    __syncthreads();
    if (tid < 128) g_tmin[(size_t)(j0 + tid) * NTILES + bi] = cmin[tid];

    if (bi != bj) {
        // mirror tile: thread has fixed i-col (tid&127), scans 64 j-rows
        float m2 = 3.4e38f;
        #pragma unroll 4
        for (int t = 0; t < 64; t++) {
            int e = t * 256 + tid;
            int r = e >> 7, c = e & 127;
            float d2 = fmaxf(srow[c] + scol[r] - 2.0f * cs[c * CSTR + r], 0.0f);
            m2 = fminf(m2, d2);
            g_d2[(size_t)(j0 + r) * N + i0 + c] = d2;
        }
        __syncthreads();
        if (tid < 128) cmin[tid] = m2;
        __syncthreads();
        if (tid >= 128) cmin[tid - 128] = fminf(cmin[tid - 128], m2);
        __syncthreads();
        if (tid < 128) g_tmin[(size_t)(i0 + tid) * NTILES + bj] = cmin[tid];
    }
}

// ---------------- GEMM 2: cosine + masks + both planes (fp16 single) -----------
__global__ __launch_bounds__(256, 2) void k_gemm_out_mma(float* __restrict__ out) {
    extern __shared__ char dsm[];
    __shared__ float rrow[128], rcol[128];
    __shared__ unsigned long long mr[128][2];
    const int tid = threadIdx.x;
    int bi, bj;
    tri_map(blockIdx.x, bi, bj);
    int i0 = bi * BM, j0 = bj * BM;
    uint32_t sbase = smem_u32(dsm);

    float acc[2][8][4];
    #pragma unroll
    for (int a = 0; a < 2; a++)
        #pragma unroll
        for (int b = 0; b < 8; b++)
            #pragma unroll
            for (int c = 0; c < 4; c++) acc[a][b][c] = 0.f;

    mma_mainloop<D2H, 1>(g_bhi, g_bhi, i0, j0, sbase, acc);

    float* cs = (float*)dsm;
    stage_c(cs, acc);
    if (tid < 128) { rrow[tid] = g_rn[i0 + tid]; rcol[tid] = g_rn[j0 + tid]; }
    mr[tid >> 1][tid & 1] = g_mask[(size_t)(i0 + (tid >> 1)) * MASKW + (j0 >> 6) + (tid & 1)];
    __syncthreads();

    float asum = (float)g_asum;
    float Nw = 0.5f / asum;
    float Nb = 1.0f / ((float)N * (float)N - 2.0f * asum);
    const size_t NN = (size_t)N * N;

    #pragma unroll 4
    for (int t = 0; t < 64; t++) {
        int e = t * 256 + tid;
        int r = e >> 7, c = e & 127;
        float C = cs[r * CSTR + c] * rrow[r] * rcol[c];
        unsigned a = (unsigned)((mr[r][c >> 6] >> (c & 63)) & 1ull);
        size_t o = (size_t)(i0 + r) * N + j0 + c;
        out[o] = a ? 0.0f : Nb * C;
        out[NN + o] = a ? Nw * C : 0.0f;
    }
    if (bi != bj) {
        #pragma unroll 4
        for (int t = 0; t < 64; t++) {
            int e = t * 256 + tid;
            int r = e >> 7, c = e & 127;
            float C = cs[c * CSTR + r] * rrow[c] * rcol[r];
            unsigned a = (unsigned)((mr[c][r >> 6] >> (r & 63)) & 1ull);
            size_t o = (size_t)(j0 + r) * N + i0 + c;
            out[o] = a ? 0.0f : Nb * C;
            out[NN + o] = a ? Nw * C : 0.0f;
        }
    }
}

// ---------------- kNN: tile-minima threshold + sparse scan ---------------------
__global__ __launch_bounds__(128) void k_knn() {
    int row = blockIdx.x, tid = threadIdx.x;
    __shared__ float shT;
    __shared__ unsigned shMask;
    __shared__ int cnt;
    __shared__ unsigned long long cand[1024];
    if (tid == 0) cnt = 0;

    if (tid < 32) {
        float tm = g_tmin[(size_t)row * NTILES + tid];
        // rank of (tm, tid) among 32 lanes, lexicographic
        int rank = 0;
        #pragma unroll
        for (int j = 0; j < 32; j++) {
            float vj = __shfl_sync(0xFFFFFFFFu, tm, j);
            rank += (vj < tm) || (vj == tm && j < tid);
        }
        unsigned bal = __ballot_sync(0xFFFFFFFFu, rank == KNN - 1);
        int src = __ffs(bal) - 1;
        float T = __shfl_sync(0xFFFFFFFFu, tm, src); // 10th smallest tile-min
        unsigned msk = __ballot_sync(0xFFFFFFFFu, tm <= T);
        if (tid == 0) { shT = T; shMask = msk; }
    }
    __syncthreads();

    // scan only tiles whose min <= T; all skipped tiles have every value > T
    float T = shT;
    unsigned msk = shMask;
    const float* dr = g_d2 + (size_t)row * N;
    while (msk) {
        int b = __ffs(msk) - 1;
        msk &= msk - 1;
        float v = dr[b * 128 + tid];
        if (v <= T) {
            int p = atomicAdd(&cnt, 1);
            if (p < 1024)
                cand[p] = ((unsigned long long)__float_as_uint(v) << 32)
                        | (unsigned)(b * 128 + tid);
        }
    }
    __syncthreads();

    if (tid == 0) {
        int m = cnt < 1024 ? cnt : 1024;
        for (int t = 0; t < KNN; t++) {
            int best = t;
            for (int u = t + 1; u < m; u++)
                if (cand[u] < cand[best]) best = u;
            unsigned long long tmp = cand[best];
            cand[best] = cand[t]; cand[t] = tmp;
            unsigned j = (unsigned)tmp;
            atomicOr(&g_mask[(size_t)row * MASKW + (j >> 6)], 1ull << (j & 63));
            atomicOr(&g_mask[(size_t)j * MASKW + (row >> 6)], 1ull << (row & 63));
        }
    }
}

__global__ void k_count() {
    int i = blockIdx.x * blockDim.x + threadIdx.x;
    int cnt = 0;
    const int total = N * MASKW;
    for (; i < total; i += gridDim.x * blockDim.x) cnt += __popcll(g_mask[i]);
    #pragma unroll
    for (int o = 16; o; o >>= 1) cnt += __shfl_down_sync(0xFFFFFFFFu, cnt, o);
    if ((threadIdx.x & 31) == 0 && cnt) atomicAdd(&g_asum, cnt);
}

// ---------------------------------------------------------------------------
extern "C" void kernel_launch(void* const* d_in, const int* in_sizes, int n_in,
                              void* d_out, int out_size) {
    const float* orig = (const float*)d_in[0]; // [4096, 512]
    const float* hid  = (const float*)d_in[1]; // [4096, 1024]
    float* out = (float*)d_out;                // [2, 4096, 4096]

    cudaFuncSetAttribute(k_gemm_d2_mma, cudaFuncAttributeMaxDynamicSharedMemorySize, DYN_SMEM);
    cudaFuncSetAttribute(k_gemm_out_mma, cudaFuncAttributeMaxDynamicSharedMemorySize, DYN_SMEM);

    k_prep<<<1024, 256>>>(orig, hid);
    k_gemm_d2_mma<<<NBLK, 256, DYN_SMEM>>>();
    k_knn<<<N, 128>>>();
    k_count<<<256, 256>>>();
    k_gemm_out_mma<<<NBLK, 256, DYN_SMEM>>>(out);
}